// round 4
// baseline (speedup 1.0000x reference)
#include <cuda_runtime.h>
#include <math.h>

// Problem dims
#define Bq   512
#define Sq   64
#define Tq   32
#define Eq   512
#define Hq   1024
#define H2q  2048
#define G3H  3072   // 3*H
#define G6H  6144   // 3*2H
#define Vq   128

// Scratch (device statics; allocation-free)
__device__ float g_encA[2][Vq][G3H];        // gi tables (incl b_ih) per direction
__device__ float g_decA[Vq][G6H];           // decoder gi table
__device__ float g_henc[2][2][Bq][Hq];      // [dir][pingpong][b][h]
__device__ float g_hdec[2][Bq][H2q];        // [pingpong][b][2h]
__device__ float g_lpart[8][Bq][Vq];        // logits K-split partials
__device__ int   g_tok[Bq];                 // current decoder tokens

__device__ __forceinline__ float sigf(float x) { return 1.0f / (1.0f + expf(-x)); }

// ---------------------------------------------------------------------------
// Projection tables: C[M=128, N] = A[128,512] @ W[N,512]^T + bias[N]
// z=0: encA fwd (N=3072), z=1: encA bwd (N=3072), z=2: decA (N=6144)
// ---------------------------------------------------------------------------
__global__ __launch_bounds__(256) void table_kernel(
    const float* __restrict__ enc_emb, const float* __restrict__ dec_emb,
    const float* __restrict__ Wf, const float* __restrict__ bf,
    const float* __restrict__ Wb, const float* __restrict__ bb,
    const float* __restrict__ Wd, const float* __restrict__ bd)
{
    int z = blockIdx.z;
    const float* A; const float* W; const float* bias; float* out; int N;
    if (z == 0)      { A = enc_emb; W = Wf; bias = bf; out = &g_encA[0][0][0]; N = G3H; }
    else if (z == 1) { A = enc_emb; W = Wb; bias = bb; out = &g_encA[1][0][0]; N = G3H; }
    else             { A = dec_emb; W = Wd; bias = bd; out = &g_decA[0][0];    N = G6H; }

    int bn = blockIdx.x * 64;
    if (bn >= N) return;
    int bm = blockIdx.y * 64;
    const int K = Eq;

    __shared__ float As[16][68];
    __shared__ float Bs[16][68];

    int tid = threadIdx.x;
    int tx = tid & 15, ty = tid >> 4;
    int lr = tid >> 2, lc = tid & 3;

    float acc[4][4];
    #pragma unroll
    for (int i = 0; i < 4; i++)
        #pragma unroll
        for (int j = 0; j < 4; j++) acc[i][j] = 0.f;

    for (int k0 = 0; k0 < K; k0 += 16) {
        float4 a4 = *(const float4*)&A[(bm + lr) * K + k0 + lc * 4];
        float4 w4 = *(const float4*)&W[(bn + lr) * K + k0 + lc * 4];
        As[lc*4+0][lr] = a4.x; As[lc*4+1][lr] = a4.y; As[lc*4+2][lr] = a4.z; As[lc*4+3][lr] = a4.w;
        Bs[lc*4+0][lr] = w4.x; Bs[lc*4+1][lr] = w4.y; Bs[lc*4+2][lr] = w4.z; Bs[lc*4+3][lr] = w4.w;
        __syncthreads();
        #pragma unroll
        for (int k = 0; k < 16; k++) {
            float4 av = *(const float4*)&As[k][ty * 4];
            float4 bv = *(const float4*)&Bs[k][tx * 4];
            float am[4] = {av.x, av.y, av.z, av.w};
            float bm4[4] = {bv.x, bv.y, bv.z, bv.w};
            #pragma unroll
            for (int i = 0; i < 4; i++)
                #pragma unroll
                for (int j = 0; j < 4; j++) acc[i][j] += am[i] * bm4[j];
        }
        __syncthreads();
    }

    #pragma unroll
    for (int i = 0; i < 4; i++) {
        int m = bm + ty * 4 + i;
        #pragma unroll
        for (int j = 0; j < 4; j++) {
            int n = bn + tx * 4 + j;
            out[m * N + n] = acc[i][j] + bias[n];
        }
    }
}

// ---------------------------------------------------------------------------
// Init: zero h0 for both encoder directions, load initial decoder tokens
// ---------------------------------------------------------------------------
__global__ void init_kernel(const int* __restrict__ tgt)
{
    int i = blockIdx.x * 256 + threadIdx.x;
    const int half = Bq * Hq;
    if (i < 2 * half) {
        int dir = i / half, off = i % half;
        (&g_henc[dir][0][0][0])[off] = 0.f;
    }
    if (i < Bq) g_tok[i] = tgt[i * Tq + 0];
}

// ---------------------------------------------------------------------------
// Encoder step (both directions, fused 3-gate GEMM + GRU update)
// gh = h @ W_hh^T + b_hh ; gates from table gi ; h' written to ping-pong buf
// ---------------------------------------------------------------------------
__global__ __launch_bounds__(256) void enc_step_kernel(
    const int* __restrict__ src,
    const float* __restrict__ Wf, const float* __restrict__ bhf,
    const float* __restrict__ Wb, const float* __restrict__ bhb, int t)
{
    const int K = Hq;
    int dir = blockIdx.z;
    const float* W   = dir ? Wb  : Wf;
    const float* bhh = dir ? bhb : bhf;
    const float* tab = &g_encA[dir][0][0];
    const float* hprev = &g_henc[dir][t & 1][0][0];
    float* hnext       = &g_henc[dir][(t + 1) & 1][0][0];
    int s = dir ? (Sq - 1 - t) : t;

    int bm = blockIdx.y * 64, bn = blockIdx.x * 64;

    __shared__ float As[16][68];
    __shared__ float Bs[3][16][68];

    int tid = threadIdx.x;
    int tx = tid & 15, ty = tid >> 4;
    int lr = tid >> 2, lc = tid & 3;

    float acc[3][4][4];
    #pragma unroll
    for (int g = 0; g < 3; g++)
        #pragma unroll
        for (int i = 0; i < 4; i++)
            #pragma unroll
            for (int j = 0; j < 4; j++) acc[g][i][j] = 0.f;

    const float* Arow = hprev + (bm + lr) * K + lc * 4;
    const float* W0 = W + (size_t)(bn + lr) * K + lc * 4;
    const float* W1 = W0 + (size_t)Hq * K;
    const float* W2 = W1 + (size_t)Hq * K;

    float4 a4 = *(const float4*)Arow;
    float4 w0 = *(const float4*)W0;
    float4 w1 = *(const float4*)W1;
    float4 w2 = *(const float4*)W2;

    for (int k0 = 0; k0 < K; k0 += 16) {
        As[lc*4+0][lr] = a4.x; As[lc*4+1][lr] = a4.y; As[lc*4+2][lr] = a4.z; As[lc*4+3][lr] = a4.w;
        Bs[0][lc*4+0][lr] = w0.x; Bs[0][lc*4+1][lr] = w0.y; Bs[0][lc*4+2][lr] = w0.z; Bs[0][lc*4+3][lr] = w0.w;
        Bs[1][lc*4+0][lr] = w1.x; Bs[1][lc*4+1][lr] = w1.y; Bs[1][lc*4+2][lr] = w1.z; Bs[1][lc*4+3][lr] = w1.w;
        Bs[2][lc*4+0][lr] = w2.x; Bs[2][lc*4+1][lr] = w2.y; Bs[2][lc*4+2][lr] = w2.z; Bs[2][lc*4+3][lr] = w2.w;
        __syncthreads();
        if (k0 + 16 < K) {
            a4 = *(const float4*)(Arow + k0 + 16);
            w0 = *(const float4*)(W0 + k0 + 16);
            w1 = *(const float4*)(W1 + k0 + 16);
            w2 = *(const float4*)(W2 + k0 + 16);
        }
        #pragma unroll
        for (int k = 0; k < 16; k++) {
            float4 av = *(const float4*)&As[k][ty * 4];
            float4 b0 = *(const float4*)&Bs[0][k][tx * 4];
            float4 b1 = *(const float4*)&Bs[1][k][tx * 4];
            float4 b2 = *(const float4*)&Bs[2][k][tx * 4];
            float am[4] = {av.x, av.y, av.z, av.w};
            float v0[4] = {b0.x, b0.y, b0.z, b0.w};
            float v1[4] = {b1.x, b1.y, b1.z, b1.w};
            float v2[4] = {b2.x, b2.y, b2.z, b2.w};
            #pragma unroll
            for (int i = 0; i < 4; i++)
                #pragma unroll
                for (int j = 0; j < 4; j++) {
                    acc[0][i][j] += am[i] * v0[j];
                    acc[1][i][j] += am[i] * v1[j];
                    acc[2][i][j] += am[i] * v2[j];
                }
        }
        __syncthreads();
    }

    #pragma unroll
    for (int i = 0; i < 4; i++) {
        int b = bm + ty * 4 + i;
        int tok = src[b * Sq + s];
        const float* gi = tab + tok * G3H;
        #pragma unroll
        for (int j = 0; j < 4; j++) {
            int n = bn + tx * 4 + j;
            float gr = acc[0][i][j] + bhh[n];
            float gz = acc[1][i][j] + bhh[n + Hq];
            float gn = acc[2][i][j] + bhh[n + 2 * Hq];
            float r  = sigf(gi[n] + gr);
            float z  = sigf(gi[n + Hq] + gz);
            float nn = tanhf(gi[n + 2 * Hq] + r * gn);
            float hp = hprev[b * K + n];
            hnext[b * K + n] = (1.f - z) * nn + z * hp;
        }
    }
}

// ---------------------------------------------------------------------------
// Concat encoder final states -> decoder h0 (buffer 0)
// ---------------------------------------------------------------------------
__global__ void concat_kernel()
{
    int i = blockIdx.x * 256 + threadIdx.x;  // < 512*2048
    int b = i >> 11, j = i & 2047;
    g_hdec[0][b][j] = (j < Hq) ? g_henc[0][0][b][j] : g_henc[1][0][b][j - Hq];
}

// ---------------------------------------------------------------------------
// Decoder step (fused 3-gate GEMM over K=2048 + GRU update)
// ---------------------------------------------------------------------------
__global__ __launch_bounds__(256) void dec_step_kernel(
    const float* __restrict__ W, const float* __restrict__ bhh, int t)
{
    const int K = H2q;
    const float* tab = &g_decA[0][0];
    const float* hprev = &g_hdec[t & 1][0][0];
    float* hnext       = &g_hdec[(t + 1) & 1][0][0];

    int bm = blockIdx.y * 64, bn = blockIdx.x * 64;

    __shared__ float As[16][68];
    __shared__ float Bs[3][16][68];

    int tid = threadIdx.x;
    int tx = tid & 15, ty = tid >> 4;
    int lr = tid >> 2, lc = tid & 3;

    float acc[3][4][4];
    #pragma unroll
    for (int g = 0; g < 3; g++)
        #pragma unroll
        for (int i = 0; i < 4; i++)
            #pragma unroll
            for (int j = 0; j < 4; j++) acc[g][i][j] = 0.f;

    const float* Arow = hprev + (bm + lr) * K + lc * 4;
    const float* W0 = W + (size_t)(bn + lr) * K + lc * 4;
    const float* W1 = W0 + (size_t)H2q * K;
    const float* W2 = W1 + (size_t)H2q * K;

    float4 a4 = *(const float4*)Arow;
    float4 w0 = *(const float4*)W0;
    float4 w1 = *(const float4*)W1;
    float4 w2 = *(const float4*)W2;

    for (int k0 = 0; k0 < K; k0 += 16) {
        As[lc*4+0][lr] = a4.x; As[lc*4+1][lr] = a4.y; As[lc*4+2][lr] = a4.z; As[lc*4+3][lr] = a4.w;
        Bs[0][lc*4+0][lr] = w0.x; Bs[0][lc*4+1][lr] = w0.y; Bs[0][lc*4+2][lr] = w0.z; Bs[0][lc*4+3][lr] = w0.w;
        Bs[1][lc*4+0][lr] = w1.x; Bs[1][lc*4+1][lr] = w1.y; Bs[1][lc*4+2][lr] = w1.z; Bs[1][lc*4+3][lr] = w1.w;
        Bs[2][lc*4+0][lr] = w2.x; Bs[2][lc*4+1][lr] = w2.y; Bs[2][lc*4+2][lr] = w2.z; Bs[2][lc*4+3][lr] = w2.w;
        __syncthreads();
        if (k0 + 16 < K) {
            a4 = *(const float4*)(Arow + k0 + 16);
            w0 = *(const float4*)(W0 + k0 + 16);
            w1 = *(const float4*)(W1 + k0 + 16);
            w2 = *(const float4*)(W2 + k0 + 16);
        }
        #pragma unroll
        for (int k = 0; k < 16; k++) {
            float4 av = *(const float4*)&As[k][ty * 4];
            float4 b0 = *(const float4*)&Bs[0][k][tx * 4];
            float4 b1 = *(const float4*)&Bs[1][k][tx * 4];
            float4 b2 = *(const float4*)&Bs[2][k][tx * 4];
            float am[4] = {av.x, av.y, av.z, av.w};
            float v0[4] = {b0.x, b0.y, b0.z, b0.w};
            float v1[4] = {b1.x, b1.y, b1.z, b1.w};
            float v2[4] = {b2.x, b2.y, b2.z, b2.w};
            #pragma unroll
            for (int i = 0; i < 4; i++)
                #pragma unroll
                for (int j = 0; j < 4; j++) {
                    acc[0][i][j] += am[i] * v0[j];
                    acc[1][i][j] += am[i] * v1[j];
                    acc[2][i][j] += am[i] * v2[j];
                }
        }
        __syncthreads();
    }

    #pragma unroll
    for (int i = 0; i < 4; i++) {
        int b = bm + ty * 4 + i;
        int tok = g_tok[b];
        const float* gi = tab + tok * G6H;
        #pragma unroll
        for (int j = 0; j < 4; j++) {
            int n = bn + tx * 4 + j;
            float gr = acc[0][i][j] + bhh[n];
            float gz = acc[1][i][j] + bhh[n + H2q];
            float gn = acc[2][i][j] + bhh[n + 2 * H2q];
            float r  = sigf(gi[n] + gr);
            float z  = sigf(gi[n + H2q] + gz);
            float nn = tanhf(gi[n + 2 * H2q] + r * gn);
            float hp = hprev[b * K + n];
            hnext[b * K + n] = (1.f - z) * nn + z * hp;
        }
    }
}

// ---------------------------------------------------------------------------
// Logits partials: K-split (x8) of h_new[512,2048] @ W_fc[128,2048]^T
// grid: (ksplit=8, mblock=8). Tile 64x128, micro 4x8.
// ---------------------------------------------------------------------------
__global__ __launch_bounds__(256) void logits_part_kernel(const float* __restrict__ Wfc, int t)
{
    const int K = H2q;
    const float* h = &g_hdec[(t + 1) & 1][0][0];
    int ks = blockIdx.x;
    int bm = blockIdx.y * 64;
    int kb = ks * 256;

    __shared__ float As[16][68];
    __shared__ float Bs[16][132];

    int tid = threadIdx.x;
    int tx = tid & 15, ty = tid >> 4;
    int lr = tid >> 2, lc = tid & 3;
    int wr = tid >> 1, wc = (tid & 1) * 8;

    float acc[4][8];
    #pragma unroll
    for (int i = 0; i < 4; i++)
        #pragma unroll
        for (int j = 0; j < 8; j++) acc[i][j] = 0.f;

    const float* Arow = h + (bm + lr) * K + kb + lc * 4;
    const float* Wrow = Wfc + wr * K + kb + wc;

    for (int k0 = 0; k0 < 256; k0 += 16) {
        float4 a4 = *(const float4*)(Arow + k0);
        float4 u0 = *(const float4*)(Wrow + k0);
        float4 u1 = *(const float4*)(Wrow + k0 + 4);
        As[lc*4+0][lr] = a4.x; As[lc*4+1][lr] = a4.y; As[lc*4+2][lr] = a4.z; As[lc*4+3][lr] = a4.w;
        Bs[wc+0][wr] = u0.x; Bs[wc+1][wr] = u0.y; Bs[wc+2][wr] = u0.z; Bs[wc+3][wr] = u0.w;
        Bs[wc+4][wr] = u1.x; Bs[wc+5][wr] = u1.y; Bs[wc+6][wr] = u1.z; Bs[wc+7][wr] = u1.w;
        __syncthreads();
        #pragma unroll
        for (int k = 0; k < 16; k++) {
            float4 av = *(const float4*)&As[k][ty * 4];
            float4 b0 = *(const float4*)&Bs[k][tx * 8];
            float4 b1 = *(const float4*)&Bs[k][tx * 8 + 4];
            float am[4] = {av.x, av.y, av.z, av.w};
            float v[8]  = {b0.x, b0.y, b0.z, b0.w, b1.x, b1.y, b1.z, b1.w};
            #pragma unroll
            for (int i = 0; i < 4; i++)
                #pragma unroll
                for (int j = 0; j < 8; j++) acc[i][j] += am[i] * v[j];
        }
        __syncthreads();
    }

    #pragma unroll
    for (int i = 0; i < 4; i++)
        #pragma unroll
        for (int j = 0; j < 8; j++)
            g_lpart[ks][bm + ty * 4 + i][tx * 8 + j] = acc[i][j];
}

// ---------------------------------------------------------------------------
// Reduce partials + bias, write logits to d_out, argmax (first-max) -> g_tok
// grid: 512 blocks x 128 threads
// ---------------------------------------------------------------------------
__global__ __launch_bounds__(128) void reduce_argmax_kernel(
    const float* __restrict__ bfc, float* __restrict__ out, int t)
{
    int b = blockIdx.x;
    int v = threadIdx.x;
    float s = bfc[v];
    #pragma unroll
    for (int ks = 0; ks < 8; ks++) s += g_lpart[ks][b][v];
    out[((size_t)b * (Tq - 1) + t) * Vq + v] = s;

    __shared__ float sv[128];
    __shared__ int   si[128];
    sv[v] = s; si[v] = v;
    __syncthreads();
    #pragma unroll
    for (int off = 64; off > 0; off >>= 1) {
        if (v < off) {
            float o = sv[v + off]; int oi = si[v + off];
            if (o > sv[v] || (o == sv[v] && oi < si[v])) { sv[v] = o; si[v] = oi; }
        }
        __syncthreads();
    }
    if (v == 0) g_tok[b] = si[0];
}

// ---------------------------------------------------------------------------
extern "C" void kernel_launch(void* const* d_in, const int* in_sizes, int n_in,
                              void* d_out, int out_size)
{
    const int*   src     = (const int*)d_in[0];
    const int*   tgt     = (const int*)d_in[1];
    const float* enc_emb = (const float*)d_in[2];
    const float* dec_emb = (const float*)d_in[3];
    const float* W_ih_f  = (const float*)d_in[4];
    const float* W_hh_f  = (const float*)d_in[5];
    const float* b_ih_f  = (const float*)d_in[6];
    const float* b_hh_f  = (const float*)d_in[7];
    const float* W_ih_b  = (const float*)d_in[8];
    const float* W_hh_b  = (const float*)d_in[9];
    const float* b_ih_b  = (const float*)d_in[10];
    const float* b_hh_b  = (const float*)d_in[11];
    const float* W_ih_d  = (const float*)d_in[12];
    const float* W_hh_d  = (const float*)d_in[13];
    const float* b_ih_d  = (const float*)d_in[14];
    const float* b_hh_d  = (const float*)d_in[15];
    const float* W_fc    = (const float*)d_in[16];
    const float* b_fc    = (const float*)d_in[17];
    float* out = (float*)d_out;

    // Projection tables (input GEMMs collapse to 128-row tables)
    table_kernel<<<dim3(96, 2, 3), 256>>>(enc_emb, dec_emb,
                                          W_ih_f, b_ih_f, W_ih_b, b_ih_b, W_ih_d, b_ih_d);
    // h0 = 0, tok0 = tgt[:,0]
    init_kernel<<<4096, 256>>>(tgt);

    // Bidirectional encoder: both directions per launch (grid.z = 2)
    for (int t = 0; t < Sq; t++)
        enc_step_kernel<<<dim3(16, 8, 2), 256>>>(src, W_hh_f, b_hh_f, W_hh_b, b_hh_b, t);

    // decoder h0 = concat(h_fwd, h_bwd)
    concat_kernel<<<4096, 256>>>();

    // Greedy decoder
    for (int t = 0; t < Tq - 1; t++) {
        dec_step_kernel<<<dim3(32, 8), 256>>>(W_hh_d, b_hh_d, t);
        logits_part_kernel<<<dim3(8, 8), 256>>>(W_fc, t);
        reduce_argmax_kernel<<<Bq, 128>>>(b_fc, out, t);
    }
}

// round 5
// speedup vs baseline: 1.0001x; 1.0001x over previous
#include <cuda_runtime.h>
#include <math.h>

// Problem dims
#define Bq   512
#define Sq   64
#define Tq   32
#define Eq   512
#define Hq   1024
#define H2q  2048
#define G3H  3072   // 3*H
#define G6H  6144   // 3*2H
#define Vq   128

// Scratch (device statics; allocation-free)
__device__ float g_encA[2][Vq][G3H];        // gi tables (incl b_ih) per direction
__device__ float g_decA[Vq][G6H];           // decoder gi table
__device__ float g_henc[2][2][Bq][Hq];      // [dir][pingpong][b][h]
__device__ float g_hdec[2][Bq][H2q];        // [pingpong][b][2h]
__device__ float g_lpart[8][Bq][Vq];        // logits K-split partials
__device__ int   g_tok[Bq];                 // current decoder tokens

__device__ __forceinline__ float sigf(float x) { return 1.0f / (1.0f + expf(-x)); }

// ---------------------------------------------------------------------------
// Projection tables: C[M=128, N] = A[128,512] @ W[N,512]^T + bias[N]
// z=0: encA fwd (N=3072), z=1: encA bwd (N=3072), z=2: decA (N=6144)
// ---------------------------------------------------------------------------
__global__ __launch_bounds__(256) void table_kernel(
    const float* __restrict__ enc_emb, const float* __restrict__ dec_emb,
    const float* __restrict__ Wf, const float* __restrict__ bf,
    const float* __restrict__ Wb, const float* __restrict__ bb,
    const float* __restrict__ Wd, const float* __restrict__ bd)
{
    int z = blockIdx.z;
    const float* A; const float* W; const float* bias; float* out; int N;
    if (z == 0)      { A = enc_emb; W = Wf; bias = bf; out = &g_encA[0][0][0]; N = G3H; }
    else if (z == 1) { A = enc_emb; W = Wb; bias = bb; out = &g_encA[1][0][0]; N = G3H; }
    else             { A = dec_emb; W = Wd; bias = bd; out = &g_decA[0][0];    N = G6H; }

    int bn = blockIdx.x * 64;
    if (bn >= N) return;
    int bm = blockIdx.y * 64;
    const int K = Eq;

    __shared__ float As[16][68];
    __shared__ float Bs[16][68];

    int tid = threadIdx.x;
    int tx = tid & 15, ty = tid >> 4;
    int lr = tid >> 2, lc = tid & 3;

    float acc[4][4];
    #pragma unroll
    for (int i = 0; i < 4; i++)
        #pragma unroll
        for (int j = 0; j < 4; j++) acc[i][j] = 0.f;

    for (int k0 = 0; k0 < K; k0 += 16) {
        float4 a4 = *(const float4*)&A[(bm + lr) * K + k0 + lc * 4];
        float4 w4 = *(const float4*)&W[(bn + lr) * K + k0 + lc * 4];
        As[lc*4+0][lr] = a4.x; As[lc*4+1][lr] = a4.y; As[lc*4+2][lr] = a4.z; As[lc*4+3][lr] = a4.w;
        Bs[lc*4+0][lr] = w4.x; Bs[lc*4+1][lr] = w4.y; Bs[lc*4+2][lr] = w4.z; Bs[lc*4+3][lr] = w4.w;
        __syncthreads();
        #pragma unroll
        for (int k = 0; k < 16; k++) {
            float4 av = *(const float4*)&As[k][ty * 4];
            float4 bv = *(const float4*)&Bs[k][tx * 4];
            float am[4] = {av.x, av.y, av.z, av.w};
            float bm4[4] = {bv.x, bv.y, bv.z, bv.w};
            #pragma unroll
            for (int i = 0; i < 4; i++)
                #pragma unroll
                for (int j = 0; j < 4; j++) acc[i][j] += am[i] * bm4[j];
        }
        __syncthreads();
    }

    #pragma unroll
    for (int i = 0; i < 4; i++) {
        int m = bm + ty * 4 + i;
        #pragma unroll
        for (int j = 0; j < 4; j++) {
            int n = bn + tx * 4 + j;
            out[m * N + n] = acc[i][j] + bias[n];
        }
    }
}

// ---------------------------------------------------------------------------
// Init: zero h0 for both encoder directions, load initial decoder tokens
// ---------------------------------------------------------------------------
__global__ void init_kernel(const int* __restrict__ tgt)
{
    int i = blockIdx.x * 256 + threadIdx.x;
    const int half = Bq * Hq;
    if (i < 2 * half) {
        int dir = i / half, off = i % half;
        (&g_henc[dir][0][0][0])[off] = 0.f;
    }
    if (i < Bq) g_tok[i] = tgt[i * Tq + 0];
}

// ---------------------------------------------------------------------------
// Encoder step (both directions, fused 3-gate GEMM + GRU update)
// gh = h @ W_hh^T + b_hh ; gates from table gi ; h' written to ping-pong buf
// ---------------------------------------------------------------------------
__global__ __launch_bounds__(256) void enc_step_kernel(
    const int* __restrict__ src,
    const float* __restrict__ Wf, const float* __restrict__ bhf,
    const float* __restrict__ Wb, const float* __restrict__ bhb, int t)
{
    const int K = Hq;
    int dir = blockIdx.z;
    const float* W   = dir ? Wb  : Wf;
    const float* bhh = dir ? bhb : bhf;
    const float* tab = &g_encA[dir][0][0];
    const float* hprev = &g_henc[dir][t & 1][0][0];
    float* hnext       = &g_henc[dir][(t + 1) & 1][0][0];
    int s = dir ? (Sq - 1 - t) : t;

    int bm = blockIdx.y * 64, bn = blockIdx.x * 64;

    __shared__ float As[16][68];
    __shared__ float Bs[3][16][68];

    int tid = threadIdx.x;
    int tx = tid & 15, ty = tid >> 4;
    int lr = tid >> 2, lc = tid & 3;

    float acc[3][4][4];
    #pragma unroll
    for (int g = 0; g < 3; g++)
        #pragma unroll
        for (int i = 0; i < 4; i++)
            #pragma unroll
            for (int j = 0; j < 4; j++) acc[g][i][j] = 0.f;

    const float* Arow = hprev + (bm + lr) * K + lc * 4;
    const float* W0 = W + (size_t)(bn + lr) * K + lc * 4;
    const float* W1 = W0 + (size_t)Hq * K;
    const float* W2 = W1 + (size_t)Hq * K;

    float4 a4 = *(const float4*)Arow;
    float4 w0 = *(const float4*)W0;
    float4 w1 = *(const float4*)W1;
    float4 w2 = *(const float4*)W2;

    for (int k0 = 0; k0 < K; k0 += 16) {
        As[lc*4+0][lr] = a4.x; As[lc*4+1][lr] = a4.y; As[lc*4+2][lr] = a4.z; As[lc*4+3][lr] = a4.w;
        Bs[0][lc*4+0][lr] = w0.x; Bs[0][lc*4+1][lr] = w0.y; Bs[0][lc*4+2][lr] = w0.z; Bs[0][lc*4+3][lr] = w0.w;
        Bs[1][lc*4+0][lr] = w1.x; Bs[1][lc*4+1][lr] = w1.y; Bs[1][lc*4+2][lr] = w1.z; Bs[1][lc*4+3][lr] = w1.w;
        Bs[2][lc*4+0][lr] = w2.x; Bs[2][lc*4+1][lr] = w2.y; Bs[2][lc*4+2][lr] = w2.z; Bs[2][lc*4+3][lr] = w2.w;
        __syncthreads();
        if (k0 + 16 < K) {
            a4 = *(const float4*)(Arow + k0 + 16);
            w0 = *(const float4*)(W0 + k0 + 16);
            w1 = *(const float4*)(W1 + k0 + 16);
            w2 = *(const float4*)(W2 + k0 + 16);
        }
        #pragma unroll
        for (int k = 0; k < 16; k++) {
            float4 av = *(const float4*)&As[k][ty * 4];
            float4 b0 = *(const float4*)&Bs[0][k][tx * 4];
            float4 b1 = *(const float4*)&Bs[1][k][tx * 4];
            float4 b2 = *(const float4*)&Bs[2][k][tx * 4];
            float am[4] = {av.x, av.y, av.z, av.w};
            float v0[4] = {b0.x, b0.y, b0.z, b0.w};
            float v1[4] = {b1.x, b1.y, b1.z, b1.w};
            float v2[4] = {b2.x, b2.y, b2.z, b2.w};
            #pragma unroll
            for (int i = 0; i < 4; i++)
                #pragma unroll
                for (int j = 0; j < 4; j++) {
                    acc[0][i][j] += am[i] * v0[j];
                    acc[1][i][j] += am[i] * v1[j];
                    acc[2][i][j] += am[i] * v2[j];
                }
        }
        __syncthreads();
    }

    #pragma unroll
    for (int i = 0; i < 4; i++) {
        int b = bm + ty * 4 + i;
        int tok = src[b * Sq + s];
        const float* gi = tab + tok * G3H;
        #pragma unroll
        for (int j = 0; j < 4; j++) {
            int n = bn + tx * 4 + j;
            float gr = acc[0][i][j] + bhh[n];
            float gz = acc[1][i][j] + bhh[n + Hq];
            float gn = acc[2][i][j] + bhh[n + 2 * Hq];
            float r  = sigf(gi[n] + gr);
            float z  = sigf(gi[n + Hq] + gz);
            float nn = tanhf(gi[n + 2 * Hq] + r * gn);
            float hp = hprev[b * K + n];
            hnext[b * K + n] = (1.f - z) * nn + z * hp;
        }
    }
}

// ---------------------------------------------------------------------------
// Concat encoder final states -> decoder h0 (buffer 0)
// ---------------------------------------------------------------------------
__global__ void concat_kernel()
{
    int i = blockIdx.x * 256 + threadIdx.x;  // < 512*2048
    int b = i >> 11, j = i & 2047;
    g_hdec[0][b][j] = (j < Hq) ? g_henc[0][0][b][j] : g_henc[1][0][b][j - Hq];
}

// ---------------------------------------------------------------------------
// Decoder step (fused 3-gate GEMM over K=2048 + GRU update)
// ---------------------------------------------------------------------------
__global__ __launch_bounds__(256) void dec_step_kernel(
    const float* __restrict__ W, const float* __restrict__ bhh, int t)
{
    const int K = H2q;
    const float* tab = &g_decA[0][0];
    const float* hprev = &g_hdec[t & 1][0][0];
    float* hnext       = &g_hdec[(t + 1) & 1][0][0];

    int bm = blockIdx.y * 64, bn = blockIdx.x * 64;

    __shared__ float As[16][68];
    __shared__ float Bs[3][16][68];

    int tid = threadIdx.x;
    int tx = tid & 15, ty = tid >> 4;
    int lr = tid >> 2, lc = tid & 3;

    float acc[3][4][4];
    #pragma unroll
    for (int g = 0; g < 3; g++)
        #pragma unroll
        for (int i = 0; i < 4; i++)
            #pragma unroll
            for (int j = 0; j < 4; j++) acc[g][i][j] = 0.f;

    const float* Arow = hprev + (bm + lr) * K + lc * 4;
    const float* W0 = W + (size_t)(bn + lr) * K + lc * 4;
    const float* W1 = W0 + (size_t)H2q * K;
    const float* W2 = W1 + (size_t)H2q * K;

    float4 a4 = *(const float4*)Arow;
    float4 w0 = *(const float4*)W0;
    float4 w1 = *(const float4*)W1;
    float4 w2 = *(const float4*)W2;

    for (int k0 = 0; k0 < K; k0 += 16) {
        As[lc*4+0][lr] = a4.x; As[lc*4+1][lr] = a4.y; As[lc*4+2][lr] = a4.z; As[lc*4+3][lr] = a4.w;
        Bs[0][lc*4+0][lr] = w0.x; Bs[0][lc*4+1][lr] = w0.y; Bs[0][lc*4+2][lr] = w0.z; Bs[0][lc*4+3][lr] = w0.w;
        Bs[1][lc*4+0][lr] = w1.x; Bs[1][lc*4+1][lr] = w1.y; Bs[1][lc*4+2][lr] = w1.z; Bs[1][lc*4+3][lr] = w1.w;
        Bs[2][lc*4+0][lr] = w2.x; Bs[2][lc*4+1][lr] = w2.y; Bs[2][lc*4+2][lr] = w2.z; Bs[2][lc*4+3][lr] = w2.w;
        __syncthreads();
        if (k0 + 16 < K) {
            a4 = *(const float4*)(Arow + k0 + 16);
            w0 = *(const float4*)(W0 + k0 + 16);
            w1 = *(const float4*)(W1 + k0 + 16);
            w2 = *(const float4*)(W2 + k0 + 16);
        }
        #pragma unroll
        for (int k = 0; k < 16; k++) {
            float4 av = *(const float4*)&As[k][ty * 4];
            float4 b0 = *(const float4*)&Bs[0][k][tx * 4];
            float4 b1 = *(const float4*)&Bs[1][k][tx * 4];
            float4 b2 = *(const float4*)&Bs[2][k][tx * 4];
            float am[4] = {av.x, av.y, av.z, av.w};
            float v0[4] = {b0.x, b0.y, b0.z, b0.w};
            float v1[4] = {b1.x, b1.y, b1.z, b1.w};
            float v2[4] = {b2.x, b2.y, b2.z, b2.w};
            #pragma unroll
            for (int i = 0; i < 4; i++)
                #pragma unroll
                for (int j = 0; j < 4; j++) {
                    acc[0][i][j] += am[i] * v0[j];
                    acc[1][i][j] += am[i] * v1[j];
                    acc[2][i][j] += am[i] * v2[j];
                }
        }
        __syncthreads();
    }

    #pragma unroll
    for (int i = 0; i < 4; i++) {
        int b = bm + ty * 4 + i;
        int tok = g_tok[b];
        const float* gi = tab + tok * G6H;
        #pragma unroll
        for (int j = 0; j < 4; j++) {
            int n = bn + tx * 4 + j;
            float gr = acc[0][i][j] + bhh[n];
            float gz = acc[1][i][j] + bhh[n + H2q];
            float gn = acc[2][i][j] + bhh[n + 2 * H2q];
            float r  = sigf(gi[n] + gr);
            float z  = sigf(gi[n + H2q] + gz);
            float nn = tanhf(gi[n + 2 * H2q] + r * gn);
            float hp = hprev[b * K + n];
            hnext[b * K + n] = (1.f - z) * nn + z * hp;
        }
    }
}

// ---------------------------------------------------------------------------
// Logits partials: K-split (x8) of h_new[512,2048] @ W_fc[128,2048]^T
// grid: (ksplit=8, mblock=8). Tile 64x128, micro 4x8.
// ---------------------------------------------------------------------------
__global__ __launch_bounds__(256) void logits_part_kernel(const float* __restrict__ Wfc, int t)
{
    const int K = H2q;
    const float* h = &g_hdec[(t + 1) & 1][0][0];
    int ks = blockIdx.x;
    int bm = blockIdx.y * 64;
    int kb = ks * 256;

    __shared__ float As[16][68];
    __shared__ float Bs[16][132];

    int tid = threadIdx.x;
    int tx = tid & 15, ty = tid >> 4;
    int lr = tid >> 2, lc = tid & 3;
    int wr = tid >> 1, wc = (tid & 1) * 8;

    float acc[4][8];
    #pragma unroll
    for (int i = 0; i < 4; i++)
        #pragma unroll
        for (int j = 0; j < 8; j++) acc[i][j] = 0.f;

    const float* Arow = h + (bm + lr) * K + kb + lc * 4;
    const float* Wrow = Wfc + wr * K + kb + wc;

    for (int k0 = 0; k0 < 256; k0 += 16) {
        float4 a4 = *(const float4*)(Arow + k0);
        float4 u0 = *(const float4*)(Wrow + k0);
        float4 u1 = *(const float4*)(Wrow + k0 + 4);
        As[lc*4+0][lr] = a4.x; As[lc*4+1][lr] = a4.y; As[lc*4+2][lr] = a4.z; As[lc*4+3][lr] = a4.w;
        Bs[wc+0][wr] = u0.x; Bs[wc+1][wr] = u0.y; Bs[wc+2][wr] = u0.z; Bs[wc+3][wr] = u0.w;
        Bs[wc+4][wr] = u1.x; Bs[wc+5][wr] = u1.y; Bs[wc+6][wr] = u1.z; Bs[wc+7][wr] = u1.w;
        __syncthreads();
        #pragma unroll
        for (int k = 0; k < 16; k++) {
            float4 av = *(const float4*)&As[k][ty * 4];
            float4 b0 = *(const float4*)&Bs[k][tx * 8];
            float4 b1 = *(const float4*)&Bs[k][tx * 8 + 4];
            float am[4] = {av.x, av.y, av.z, av.w};
            float v[8]  = {b0.x, b0.y, b0.z, b0.w, b1.x, b1.y, b1.z, b1.w};
            #pragma unroll
            for (int i = 0; i < 4; i++)
                #pragma unroll
                for (int j = 0; j < 8; j++) acc[i][j] += am[i] * v[j];
        }
        __syncthreads();
    }

    #pragma unroll
    for (int i = 0; i < 4; i++)
        #pragma unroll
        for (int j = 0; j < 8; j++)
            g_lpart[ks][bm + ty * 4 + i][tx * 8 + j] = acc[i][j];
}

// ---------------------------------------------------------------------------
// Reduce partials + bias, write logits to d_out, argmax (first-max) -> g_tok
// grid: 512 blocks x 128 threads
// ---------------------------------------------------------------------------
__global__ __launch_bounds__(128) void reduce_argmax_kernel(
    const float* __restrict__ bfc, float* __restrict__ out, int t)
{
    int b = blockIdx.x;
    int v = threadIdx.x;
    float s = bfc[v];
    #pragma unroll
    for (int ks = 0; ks < 8; ks++) s += g_lpart[ks][b][v];
    out[((size_t)b * (Tq - 1) + t) * Vq + v] = s;

    __shared__ float sv[128];
    __shared__ int   si[128];
    sv[v] = s; si[v] = v;
    __syncthreads();
    #pragma unroll
    for (int off = 64; off > 0; off >>= 1) {
        if (v < off) {
            float o = sv[v + off]; int oi = si[v + off];
            if (o > sv[v] || (o == sv[v] && oi < si[v])) { sv[v] = o; si[v] = oi; }
        }
        __syncthreads();
    }
    if (v == 0) g_tok[b] = si[0];
}

// ---------------------------------------------------------------------------
extern "C" void kernel_launch(void* const* d_in, const int* in_sizes, int n_in,
                              void* d_out, int out_size)
{
    const int*   src     = (const int*)d_in[0];
    const int*   tgt     = (const int*)d_in[1];
    const float* enc_emb = (const float*)d_in[2];
    const float* dec_emb = (const float*)d_in[3];
    const float* W_ih_f  = (const float*)d_in[4];
    const float* W_hh_f  = (const float*)d_in[5];
    const float* b_ih_f  = (const float*)d_in[6];
    const float* b_hh_f  = (const float*)d_in[7];
    const float* W_ih_b  = (const float*)d_in[8];
    const float* W_hh_b  = (const float*)d_in[9];
    const float* b_ih_b  = (const float*)d_in[10];
    const float* b_hh_b  = (const float*)d_in[11];
    const float* W_ih_d  = (const float*)d_in[12];
    const float* W_hh_d  = (const float*)d_in[13];
    const float* b_ih_d  = (const float*)d_in[14];
    const float* b_hh_d  = (const float*)d_in[15];
    const float* W_fc    = (const float*)d_in[16];
    const float* b_fc    = (const float*)d_in[17];
    float* out = (float*)d_out;

    // Projection tables (input GEMMs collapse to 128-row tables)
    table_kernel<<<dim3(96, 2, 3), 256>>>(enc_emb, dec_emb,
                                          W_ih_f, b_ih_f, W_ih_b, b_ih_b, W_ih_d, b_ih_d);
    // h0 = 0, tok0 = tgt[:,0]
    init_kernel<<<4096, 256>>>(tgt);

    // Bidirectional encoder: both directions per launch (grid.z = 2)
    for (int t = 0; t < Sq; t++)
        enc_step_kernel<<<dim3(16, 8, 2), 256>>>(src, W_hh_f, b_hh_f, W_hh_b, b_hh_b, t);

    // decoder h0 = concat(h_fwd, h_bwd)
    concat_kernel<<<4096, 256>>>();

    // Greedy decoder
    for (int t = 0; t < Tq - 1; t++) {
        dec_step_kernel<<<dim3(32, 8), 256>>>(W_hh_d, b_hh_d, t);
        logits_part_kernel<<<dim3(8, 8), 256>>>(W_fc, t);
        reduce_argmax_kernel<<<Bq, 128>>>(b_fc, out, t);
    }
}

// round 6
// speedup vs baseline: 1.0385x; 1.0384x over previous
#include <cuda_runtime.h>
#include <math.h>

// Problem dims
#define Bq   512
#define Sq   64
#define Tq   32
#define Eq   512
#define Hq   1024
#define H2q  2048
#define G3H  3072   // 3*H
#define G6H  6144   // 3*2H
#define Vq   128

typedef unsigned long long u64;

// Packed fp32x2 FMA (SASS FFMA2 — only reachable via PTX)
__device__ __forceinline__ u64 ffma2(u64 a, u64 b, u64 c) {
    u64 d;
    asm("fma.rn.f32x2 %0, %1, %2, %3;" : "=l"(d) : "l"(a), "l"(b), "l"(c));
    return d;
}
__device__ __forceinline__ u64 pack2(float x) {
    u64 d;
    unsigned u = __float_as_uint(x);
    asm("mov.b64 %0, {%1, %1};" : "=l"(d) : "r"(u));
    return d;
}
__device__ __forceinline__ float lo32(u64 d) { return __uint_as_float((unsigned)d); }
__device__ __forceinline__ float hi32(u64 d) { return __uint_as_float((unsigned)(d >> 32)); }

// Scratch (device statics; allocation-free)
__device__ float g_encA[2][Vq][G3H];        // gi tables (incl b_ih) per direction
__device__ float g_decA[Vq][G6H];           // decoder gi table
__device__ float g_henc[2][2][Bq][Hq];      // [dir][pingpong][b][h]
__device__ float g_hdec[2][Bq][H2q];        // [pingpong][b][2h]
__device__ float g_lpart[8][Bq][Vq];        // logits K-split partials
__device__ int   g_tok[Bq];                 // current decoder tokens

__device__ __forceinline__ float sigf(float x) { return 1.0f / (1.0f + expf(-x)); }

// ---------------------------------------------------------------------------
// Projection tables: C[M=128, N] = A[128,512] @ W[N,512]^T + bias[N]
// z=0: encA fwd (N=3072), z=1: encA bwd (N=3072), z=2: decA (N=6144)
// ---------------------------------------------------------------------------
__global__ __launch_bounds__(256) void table_kernel(
    const float* __restrict__ enc_emb, const float* __restrict__ dec_emb,
    const float* __restrict__ Wf, const float* __restrict__ bf,
    const float* __restrict__ Wb, const float* __restrict__ bb,
    const float* __restrict__ Wd, const float* __restrict__ bd)
{
    int z = blockIdx.z;
    const float* A; const float* W; const float* bias; float* out; int N;
    if (z == 0)      { A = enc_emb; W = Wf; bias = bf; out = &g_encA[0][0][0]; N = G3H; }
    else if (z == 1) { A = enc_emb; W = Wb; bias = bb; out = &g_encA[1][0][0]; N = G3H; }
    else             { A = dec_emb; W = Wd; bias = bd; out = &g_decA[0][0];    N = G6H; }

    int bn = blockIdx.x * 64;
    if (bn >= N) return;
    int bm = blockIdx.y * 64;
    const int K = Eq;

    __shared__ float As[16][68];
    __shared__ float Bs[16][68];

    int tid = threadIdx.x;
    int tx = tid & 15, ty = tid >> 4;
    int lr = tid >> 2, lc = tid & 3;

    float acc[4][4];
    #pragma unroll
    for (int i = 0; i < 4; i++)
        #pragma unroll
        for (int j = 0; j < 4; j++) acc[i][j] = 0.f;

    for (int k0 = 0; k0 < K; k0 += 16) {
        float4 a4 = *(const float4*)&A[(bm + lr) * K + k0 + lc * 4];
        float4 w4 = *(const float4*)&W[(bn + lr) * K + k0 + lc * 4];
        As[lc*4+0][lr] = a4.x; As[lc*4+1][lr] = a4.y; As[lc*4+2][lr] = a4.z; As[lc*4+3][lr] = a4.w;
        Bs[lc*4+0][lr] = w4.x; Bs[lc*4+1][lr] = w4.y; Bs[lc*4+2][lr] = w4.z; Bs[lc*4+3][lr] = w4.w;
        __syncthreads();
        #pragma unroll
        for (int k = 0; k < 16; k++) {
            float4 av = *(const float4*)&As[k][ty * 4];
            float4 bv = *(const float4*)&Bs[k][tx * 4];
            float am[4] = {av.x, av.y, av.z, av.w};
            float bm4[4] = {bv.x, bv.y, bv.z, bv.w};
            #pragma unroll
            for (int i = 0; i < 4; i++)
                #pragma unroll
                for (int j = 0; j < 4; j++) acc[i][j] += am[i] * bm4[j];
        }
        __syncthreads();
    }

    #pragma unroll
    for (int i = 0; i < 4; i++) {
        int m = bm + ty * 4 + i;
        #pragma unroll
        for (int j = 0; j < 4; j++) {
            int n = bn + tx * 4 + j;
            out[m * N + n] = acc[i][j] + bias[n];
        }
    }
}

// ---------------------------------------------------------------------------
// Init: zero h0 for both encoder directions, load initial decoder tokens
// ---------------------------------------------------------------------------
__global__ void init_kernel(const int* __restrict__ tgt)
{
    int i = blockIdx.x * 256 + threadIdx.x;
    const int half = Bq * Hq;
    if (i < 2 * half) {
        int dir = i / half, off = i % half;
        (&g_henc[dir][0][0][0])[off] = 0.f;
    }
    if (i < Bq) g_tok[i] = tgt[i * Tq + 0];
}

// ---------------------------------------------------------------------------
// Encoder step (both directions, fused 3-gate GEMM + GRU update)
// Packed f32x2 mainloop: 24 FFMA2 per k instead of 48 FFMA.
// ---------------------------------------------------------------------------
__global__ __launch_bounds__(256) void enc_step_kernel(
    const int* __restrict__ src,
    const float* __restrict__ Wf, const float* __restrict__ bhf,
    const float* __restrict__ Wb, const float* __restrict__ bhb, int t)
{
    const int K = Hq;
    int dir = blockIdx.z;
    const float* W   = dir ? Wb  : Wf;
    const float* bhh = dir ? bhb : bhf;
    const float* tab = &g_encA[dir][0][0];
    const float* hprev = &g_henc[dir][t & 1][0][0];
    float* hnext       = &g_henc[dir][(t + 1) & 1][0][0];
    int s = dir ? (Sq - 1 - t) : t;

    int bm = blockIdx.y * 64, bn = blockIdx.x * 64;

    __shared__ float As[16][68];
    __shared__ float Bs[3][16][68];

    int tid = threadIdx.x;
    int tx = tid & 15, ty = tid >> 4;
    int lr = tid >> 2, lc = tid & 3;

    u64 acc[3][4][2];
    #pragma unroll
    for (int g = 0; g < 3; g++)
        #pragma unroll
        for (int i = 0; i < 4; i++)
            #pragma unroll
            for (int p = 0; p < 2; p++) acc[g][i][p] = 0ull;

    const float* Arow = hprev + (bm + lr) * K + lc * 4;
    const float* W0 = W + (size_t)(bn + lr) * K + lc * 4;
    const float* W1 = W0 + (size_t)Hq * K;
    const float* W2 = W1 + (size_t)Hq * K;

    float4 a4 = *(const float4*)Arow;
    float4 w0 = *(const float4*)W0;
    float4 w1 = *(const float4*)W1;
    float4 w2 = *(const float4*)W2;

    for (int k0 = 0; k0 < K; k0 += 16) {
        As[lc*4+0][lr] = a4.x; As[lc*4+1][lr] = a4.y; As[lc*4+2][lr] = a4.z; As[lc*4+3][lr] = a4.w;
        Bs[0][lc*4+0][lr] = w0.x; Bs[0][lc*4+1][lr] = w0.y; Bs[0][lc*4+2][lr] = w0.z; Bs[0][lc*4+3][lr] = w0.w;
        Bs[1][lc*4+0][lr] = w1.x; Bs[1][lc*4+1][lr] = w1.y; Bs[1][lc*4+2][lr] = w1.z; Bs[1][lc*4+3][lr] = w1.w;
        Bs[2][lc*4+0][lr] = w2.x; Bs[2][lc*4+1][lr] = w2.y; Bs[2][lc*4+2][lr] = w2.z; Bs[2][lc*4+3][lr] = w2.w;
        __syncthreads();
        if (k0 + 16 < K) {
            a4 = *(const float4*)(Arow + k0 + 16);
            w0 = *(const float4*)(W0 + k0 + 16);
            w1 = *(const float4*)(W1 + k0 + 16);
            w2 = *(const float4*)(W2 + k0 + 16);
        }
        #pragma unroll
        for (int k = 0; k < 16; k++) {
            float4 av = *(const float4*)&As[k][ty * 4];
            u64 aa[4] = {pack2(av.x), pack2(av.y), pack2(av.z), pack2(av.w)};
            ulonglong2 p0 = *(const ulonglong2*)&Bs[0][k][tx * 4];
            ulonglong2 p1 = *(const ulonglong2*)&Bs[1][k][tx * 4];
            ulonglong2 p2 = *(const ulonglong2*)&Bs[2][k][tx * 4];
            #pragma unroll
            for (int i = 0; i < 4; i++) {
                acc[0][i][0] = ffma2(aa[i], p0.x, acc[0][i][0]);
                acc[0][i][1] = ffma2(aa[i], p0.y, acc[0][i][1]);
                acc[1][i][0] = ffma2(aa[i], p1.x, acc[1][i][0]);
                acc[1][i][1] = ffma2(aa[i], p1.y, acc[1][i][1]);
                acc[2][i][0] = ffma2(aa[i], p2.x, acc[2][i][0]);
                acc[2][i][1] = ffma2(aa[i], p2.y, acc[2][i][1]);
            }
        }
        __syncthreads();
    }

    #pragma unroll
    for (int i = 0; i < 4; i++) {
        int b = bm + ty * 4 + i;
        int tok = src[b * Sq + s];
        const float* gi = tab + tok * G3H;
        #pragma unroll
        for (int p = 0; p < 2; p++) {
            float a0[2] = {lo32(acc[0][i][p]), hi32(acc[0][i][p])};
            float a1[2] = {lo32(acc[1][i][p]), hi32(acc[1][i][p])};
            float a2[2] = {lo32(acc[2][i][p]), hi32(acc[2][i][p])};
            #pragma unroll
            for (int q = 0; q < 2; q++) {
                int n = bn + tx * 4 + p * 2 + q;
                float gr = a0[q] + bhh[n];
                float gz = a1[q] + bhh[n + Hq];
                float gn = a2[q] + bhh[n + 2 * Hq];
                float r  = sigf(gi[n] + gr);
                float z  = sigf(gi[n + Hq] + gz);
                float nn = tanhf(gi[n + 2 * Hq] + r * gn);
                float hp = hprev[b * K + n];
                hnext[b * K + n] = (1.f - z) * nn + z * hp;
            }
        }
    }
}

// ---------------------------------------------------------------------------
// Concat encoder final states -> decoder h0 (buffer 0)
// ---------------------------------------------------------------------------
__global__ void concat_kernel()
{
    int i = blockIdx.x * 256 + threadIdx.x;  // < 512*2048
    int b = i >> 11, j = i & 2047;
    g_hdec[0][b][j] = (j < Hq) ? g_henc[0][0][b][j] : g_henc[1][0][b][j - Hq];
}

// ---------------------------------------------------------------------------
// Decoder step (fused 3-gate GEMM over K=2048 + GRU update), f32x2 mainloop
// ---------------------------------------------------------------------------
__global__ __launch_bounds__(256) void dec_step_kernel(
    const float* __restrict__ W, const float* __restrict__ bhh, int t)
{
    const int K = H2q;
    const float* tab = &g_decA[0][0];
    const float* hprev = &g_hdec[t & 1][0][0];
    float* hnext       = &g_hdec[(t + 1) & 1][0][0];

    int bm = blockIdx.y * 64, bn = blockIdx.x * 64;

    __shared__ float As[16][68];
    __shared__ float Bs[3][16][68];

    int tid = threadIdx.x;
    int tx = tid & 15, ty = tid >> 4;
    int lr = tid >> 2, lc = tid & 3;

    u64 acc[3][4][2];
    #pragma unroll
    for (int g = 0; g < 3; g++)
        #pragma unroll
        for (int i = 0; i < 4; i++)
            #pragma unroll
            for (int p = 0; p < 2; p++) acc[g][i][p] = 0ull;

    const float* Arow = hprev + (bm + lr) * K + lc * 4;
    const float* W0 = W + (size_t)(bn + lr) * K + lc * 4;
    const float* W1 = W0 + (size_t)H2q * K;
    const float* W2 = W1 + (size_t)H2q * K;

    float4 a4 = *(const float4*)Arow;
    float4 w0 = *(const float4*)W0;
    float4 w1 = *(const float4*)W1;
    float4 w2 = *(const float4*)W2;

    for (int k0 = 0; k0 < K; k0 += 16) {
        As[lc*4+0][lr] = a4.x; As[lc*4+1][lr] = a4.y; As[lc*4+2][lr] = a4.z; As[lc*4+3][lr] = a4.w;
        Bs[0][lc*4+0][lr] = w0.x; Bs[0][lc*4+1][lr] = w0.y; Bs[0][lc*4+2][lr] = w0.z; Bs[0][lc*4+3][lr] = w0.w;
        Bs[1][lc*4+0][lr] = w1.x; Bs[1][lc*4+1][lr] = w1.y; Bs[1][lc*4+2][lr] = w1.z; Bs[1][lc*4+3][lr] = w1.w;
        Bs[2][lc*4+0][lr] = w2.x; Bs[2][lc*4+1][lr] = w2.y; Bs[2][lc*4+2][lr] = w2.z; Bs[2][lc*4+3][lr] = w2.w;
        __syncthreads();
        if (k0 + 16 < K) {
            a4 = *(const float4*)(Arow + k0 + 16);
            w0 = *(const float4*)(W0 + k0 + 16);
            w1 = *(const float4*)(W1 + k0 + 16);
            w2 = *(const float4*)(W2 + k0 + 16);
        }
        #pragma unroll
        for (int k = 0; k < 16; k++) {
            float4 av = *(const float4*)&As[k][ty * 4];
            u64 aa[4] = {pack2(av.x), pack2(av.y), pack2(av.z), pack2(av.w)};
            ulonglong2 p0 = *(const ulonglong2*)&Bs[0][k][tx * 4];
            ulonglong2 p1 = *(const ulonglong2*)&Bs[1][k][tx * 4];
            ulonglong2 p2 = *(const ulonglong2*)&Bs[2][k][tx * 4];
            #pragma unroll
            for (int i = 0; i < 4; i++) {
                acc[0][i][0] = ffma2(aa[i], p0.x, acc[0][i][0]);
                acc[0][i][1] = ffma2(aa[i], p0.y, acc[0][i][1]);
                acc[1][i][0] = ffma2(aa[i], p1.x, acc[1][i][0]);
                acc[1][i][1] = ffma2(aa[i], p1.y, acc[1][i][1]);
                acc[2][i][0] = ffma2(aa[i], p2.x, acc[2][i][0]);
                acc[2][i][1] = ffma2(aa[i], p2.y, acc[2][i][1]);
            }
        }
        __syncthreads();
    }

    #pragma unroll
    for (int i = 0; i < 4; i++) {
        int b = bm + ty * 4 + i;
        int tok = g_tok[b];
        const float* gi = tab + tok * G6H;
        #pragma unroll
        for (int p = 0; p < 2; p++) {
            float a0[2] = {lo32(acc[0][i][p]), hi32(acc[0][i][p])};
            float a1[2] = {lo32(acc[1][i][p]), hi32(acc[1][i][p])};
            float a2[2] = {lo32(acc[2][i][p]), hi32(acc[2][i][p])};
            #pragma unroll
            for (int q = 0; q < 2; q++) {
                int n = bn + tx * 4 + p * 2 + q;
                float gr = a0[q] + bhh[n];
                float gz = a1[q] + bhh[n + H2q];
                float gn = a2[q] + bhh[n + 2 * H2q];
                float r  = sigf(gi[n] + gr);
                float z  = sigf(gi[n + H2q] + gz);
                float nn = tanhf(gi[n + 2 * H2q] + r * gn);
                float hp = hprev[b * K + n];
                hnext[b * K + n] = (1.f - z) * nn + z * hp;
            }
        }
    }
}

// ---------------------------------------------------------------------------
// Logits partials: K-split (x8) of h_new[512,2048] @ W_fc[128,2048]^T
// grid: (ksplit=8, mblock=8). Tile 64x128, micro 4x8 (4 packed pairs).
// ---------------------------------------------------------------------------
__global__ __launch_bounds__(256) void logits_part_kernel(const float* __restrict__ Wfc, int t)
{
    const int K = H2q;
    const float* h = &g_hdec[(t + 1) & 1][0][0];
    int ks = blockIdx.x;
    int bm = blockIdx.y * 64;
    int kb = ks * 256;

    __shared__ float As[16][68];
    __shared__ float Bs[16][132];

    int tid = threadIdx.x;
    int tx = tid & 15, ty = tid >> 4;
    int lr = tid >> 2, lc = tid & 3;
    int wr = tid >> 1, wc = (tid & 1) * 8;

    u64 acc[4][4];
    #pragma unroll
    for (int i = 0; i < 4; i++)
        #pragma unroll
        for (int p = 0; p < 4; p++) acc[i][p] = 0ull;

    const float* Arow = h + (bm + lr) * K + kb + lc * 4;
    const float* Wrow = Wfc + wr * K + kb + wc;

    for (int k0 = 0; k0 < 256; k0 += 16) {
        float4 a4 = *(const float4*)(Arow + k0);
        float4 u0 = *(const float4*)(Wrow + k0);
        float4 u1 = *(const float4*)(Wrow + k0 + 4);
        As[lc*4+0][lr] = a4.x; As[lc*4+1][lr] = a4.y; As[lc*4+2][lr] = a4.z; As[lc*4+3][lr] = a4.w;
        Bs[wc+0][wr] = u0.x; Bs[wc+1][wr] = u0.y; Bs[wc+2][wr] = u0.z; Bs[wc+3][wr] = u0.w;
        Bs[wc+4][wr] = u1.x; Bs[wc+5][wr] = u1.y; Bs[wc+6][wr] = u1.z; Bs[wc+7][wr] = u1.w;
        __syncthreads();
        #pragma unroll
        for (int k = 0; k < 16; k++) {
            float4 av = *(const float4*)&As[k][ty * 4];
            u64 aa[4] = {pack2(av.x), pack2(av.y), pack2(av.z), pack2(av.w)};
            ulonglong2 b0 = *(const ulonglong2*)&Bs[k][tx * 8];
            ulonglong2 b1 = *(const ulonglong2*)&Bs[k][tx * 8 + 4];
            #pragma unroll
            for (int i = 0; i < 4; i++) {
                acc[i][0] = ffma2(aa[i], b0.x, acc[i][0]);
                acc[i][1] = ffma2(aa[i], b0.y, acc[i][1]);
                acc[i][2] = ffma2(aa[i], b1.x, acc[i][2]);
                acc[i][3] = ffma2(aa[i], b1.y, acc[i][3]);
            }
        }
        __syncthreads();
    }

    #pragma unroll
    for (int i = 0; i < 4; i++)
        #pragma unroll
        for (int p = 0; p < 4; p++) {
            g_lpart[ks][bm + ty * 4 + i][tx * 8 + 2 * p]     = lo32(acc[i][p]);
            g_lpart[ks][bm + ty * 4 + i][tx * 8 + 2 * p + 1] = hi32(acc[i][p]);
        }
}

// ---------------------------------------------------------------------------
// Reduce partials + bias, write logits to d_out, argmax (first-max) -> g_tok
// grid: 512 blocks x 128 threads
// ---------------------------------------------------------------------------
__global__ __launch_bounds__(128) void reduce_argmax_kernel(
    const float* __restrict__ bfc, float* __restrict__ out, int t)
{
    int b = blockIdx.x;
    int v = threadIdx.x;
    float s = bfc[v];
    #pragma unroll
    for (int ks = 0; ks < 8; ks++) s += g_lpart[ks][b][v];
    out[((size_t)b * (Tq - 1) + t) * Vq + v] = s;

    __shared__ float sv[128];
    __shared__ int   si[128];
    sv[v] = s; si[v] = v;
    __syncthreads();
    #pragma unroll
    for (int off = 64; off > 0; off >>= 1) {
        if (v < off) {
            float o = sv[v + off]; int oi = si[v + off];
            if (o > sv[v] || (o == sv[v] && oi < si[v])) { sv[v] = o; si[v] = oi; }
        }
        __syncthreads();
    }
    if (v == 0) g_tok[b] = si[0];
}

// ---------------------------------------------------------------------------
extern "C" void kernel_launch(void* const* d_in, const int* in_sizes, int n_in,
                              void* d_out, int out_size)
{
    const int*   src     = (const int*)d_in[0];
    const int*   tgt     = (const int*)d_in[1];
    const float* enc_emb = (const float*)d_in[2];
    const float* dec_emb = (const float*)d_in[3];
    const float* W_ih_f  = (const float*)d_in[4];
    const float* W_hh_f  = (const float*)d_in[5];
    const float* b_ih_f  = (const float*)d_in[6];
    const float* b_hh_f  = (const float*)d_in[7];
    const float* W_ih_b  = (const float*)d_in[8];
    const float* W_hh_b  = (const float*)d_in[9];
    const float* b_ih_b  = (const float*)d_in[10];
    const float* b_hh_b  = (const float*)d_in[11];
    const float* W_ih_d  = (const float*)d_in[12];
    const float* W_hh_d  = (const float*)d_in[13];
    const float* b_ih_d  = (const float*)d_in[14];
    const float* b_hh_d  = (const float*)d_in[15];
    const float* W_fc    = (const float*)d_in[16];
    const float* b_fc    = (const float*)d_in[17];
    float* out = (float*)d_out;

    // Projection tables (input GEMMs collapse to 128-row tables)
    table_kernel<<<dim3(96, 2, 3), 256>>>(enc_emb, dec_emb,
                                          W_ih_f, b_ih_f, W_ih_b, b_ih_b, W_ih_d, b_ih_d);
    // h0 = 0, tok0 = tgt[:,0]
    init_kernel<<<4096, 256>>>(tgt);

    // Bidirectional encoder: both directions per launch (grid.z = 2)
    for (int t = 0; t < Sq; t++)
        enc_step_kernel<<<dim3(16, 8, 2), 256>>>(src, W_hh_f, b_hh_f, W_hh_b, b_hh_b, t);

    // decoder h0 = concat(h_fwd, h_bwd)
    concat_kernel<<<4096, 256>>>();

    // Greedy decoder
    for (int t = 0; t < Tq - 1; t++) {
        dec_step_kernel<<<dim3(32, 8), 256>>>(W_hh_d, b_hh_d, t);
        logits_part_kernel<<<dim3(8, 8), 256>>>(W_fc, t);
        reduce_argmax_kernel<<<Bq, 128>>>(b_fc, out, t);
    }
}

// round 9
// speedup vs baseline: 1.7989x; 1.7322x over previous
#include <cuda_runtime.h>
#include <cuda_bf16.h>
#include <math.h>

// Problem dims
#define Bq   512
#define Sq   64
#define Tq   32
#define Eq   512
#define Hq   1024
#define H2q  2048
#define G3H  3072   // 3*H
#define G6H  6144   // 3*2H
#define Vq   128

typedef unsigned long long u64;
typedef unsigned int u32;

// ---------------------------------------------------------------------------
// Scratch (device statics; allocation-free)
// ---------------------------------------------------------------------------
__device__ float g_encA[2][Vq][G3H];        // gi tables (incl b_ih) per direction
__device__ float g_decA[Vq][G6H];           // decoder gi table
__device__ float g_lpart[8][Bq][Vq];        // logits K-split partials
__device__ int   g_tok[Bq];                 // current decoder tokens

// fp32 hidden states (in-place updated)
__device__ float g_h_e[2][Bq][Hq];
__device__ float g_hdec_f[Bq][H2q];

// bf16 hi/lo split operands
__device__ __nv_bfloat16 g_hhi_e[2][Bq][Hq], g_hlo_e[2][Bq][Hq];
__device__ __nv_bfloat16 g_hhi_d[Bq][H2q],  g_hlo_d[Bq][H2q];
__device__ __nv_bfloat16 g_Whi_e[2][G3H][Hq], g_Wlo_e[2][G3H][Hq];
__device__ __nv_bfloat16 g_Whi_d[G6H][H2q],   g_Wlo_d[G6H][H2q];

// GEMM output scratch: gh = h @ W_hh^T (no bias)
__device__ float g_gh_e[2][Bq][G3H];
__device__ float g_gh_d[Bq][G6H];

// ---------------------------------------------------------------------------
// Helpers
// ---------------------------------------------------------------------------
__device__ __forceinline__ float sigf(float x) { return 1.0f / (1.0f + expf(-x)); }

__device__ __forceinline__ u32 smem_u32(const void* p) {
    u32 a;
    asm("{ .reg .u64 t; cvta.to.shared.u64 t, %1; cvt.u32.u64 %0, t; }" : "=r"(a) : "l"(p));
    return a;
}
__device__ __forceinline__ u32 swz(u32 o) { return o ^ ((o >> 3) & 0x70); }

__device__ __forceinline__ void cp16(u32 saddr, const void* gaddr) {
    asm volatile("cp.async.cg.shared.global [%0], [%1], 16;" :: "r"(saddr), "l"(gaddr) : "memory");
}
__device__ __forceinline__ void cp_commit() {
    asm volatile("cp.async.commit_group;" ::: "memory");
}
__device__ __forceinline__ void cp_wait1() {
    asm volatile("cp.async.wait_group 1;" ::: "memory");
}
__device__ __forceinline__ void cp_wait0() {
    asm volatile("cp.async.wait_group 0;" ::: "memory");
}
__device__ __forceinline__ void ldsm4(u32 addr, u32& r0, u32& r1, u32& r2, u32& r3) {
    asm volatile("ldmatrix.sync.aligned.m8n8.x4.shared.b16 {%0,%1,%2,%3}, [%4];"
                 : "=r"(r0), "=r"(r1), "=r"(r2), "=r"(r3) : "r"(addr));
}
__device__ __forceinline__ void mma16816(float* c, const u32* a, u32 b0, u32 b1) {
    asm volatile(
        "mma.sync.aligned.m16n8k16.row.col.f32.bf16.bf16.f32 "
        "{%0,%1,%2,%3}, {%4,%5,%6,%7}, {%8,%9}, {%0,%1,%2,%3};"
        : "+f"(c[0]), "+f"(c[1]), "+f"(c[2]), "+f"(c[3])
        : "r"(a[0]), "r"(a[1]), "r"(a[2]), "r"(a[3]), "r"(b0), "r"(b1));
}

// ---------------------------------------------------------------------------
// Projection tables: C[M=128, N] = A[128,512] @ W[N,512]^T + bias[N]
// ---------------------------------------------------------------------------
__global__ __launch_bounds__(256) void table_kernel(
    const float* __restrict__ enc_emb, const float* __restrict__ dec_emb,
    const float* __restrict__ Wf, const float* __restrict__ bf,
    const float* __restrict__ Wb, const float* __restrict__ bb,
    const float* __restrict__ Wd, const float* __restrict__ bd)
{
    int z = blockIdx.z;
    const float* A; const float* W; const float* bias; float* out; int N;
    if (z == 0)      { A = enc_emb; W = Wf; bias = bf; out = &g_encA[0][0][0]; N = G3H; }
    else if (z == 1) { A = enc_emb; W = Wb; bias = bb; out = &g_encA[1][0][0]; N = G3H; }
    else             { A = dec_emb; W = Wd; bias = bd; out = &g_decA[0][0];    N = G6H; }

    int bn = blockIdx.x * 64;
    if (bn >= N) return;
    int bm = blockIdx.y * 64;
    const int K = Eq;

    __shared__ float As[16][68];
    __shared__ float Bs[16][68];

    int tid = threadIdx.x;
    int tx = tid & 15, ty = tid >> 4;
    int lr = tid >> 2, lc = tid & 3;

    float acc[4][4];
    #pragma unroll
    for (int i = 0; i < 4; i++)
        #pragma unroll
        for (int j = 0; j < 4; j++) acc[i][j] = 0.f;

    for (int k0 = 0; k0 < K; k0 += 16) {
        float4 a4 = *(const float4*)&A[(bm + lr) * K + k0 + lc * 4];
        float4 w4 = *(const float4*)&W[(bn + lr) * K + k0 + lc * 4];
        As[lc*4+0][lr] = a4.x; As[lc*4+1][lr] = a4.y; As[lc*4+2][lr] = a4.z; As[lc*4+3][lr] = a4.w;
        Bs[lc*4+0][lr] = w4.x; Bs[lc*4+1][lr] = w4.y; Bs[lc*4+2][lr] = w4.z; Bs[lc*4+3][lr] = w4.w;
        __syncthreads();
        #pragma unroll
        for (int k = 0; k < 16; k++) {
            float4 av = *(const float4*)&As[k][ty * 4];
            float4 bv = *(const float4*)&Bs[k][tx * 4];
            float am[4] = {av.x, av.y, av.z, av.w};
            float bm4[4] = {bv.x, bv.y, bv.z, bv.w};
            #pragma unroll
            for (int i = 0; i < 4; i++)
                #pragma unroll
                for (int j = 0; j < 4; j++) acc[i][j] += am[i] * bm4[j];
        }
        __syncthreads();
    }

    #pragma unroll
    for (int i = 0; i < 4; i++) {
        int m = bm + ty * 4 + i;
        #pragma unroll
        for (int j = 0; j < 4; j++) {
            int n = bn + tx * 4 + j;
            out[m * N + n] = acc[i][j] + bias[n];
        }
    }
}

// ---------------------------------------------------------------------------
// Weight split: fp32 -> bf16 hi + bf16 lo
// ---------------------------------------------------------------------------
__global__ void wsplit_kernel(const float* __restrict__ w,
                              __nv_bfloat16* __restrict__ hi,
                              __nv_bfloat16* __restrict__ lo, int n)
{
    int i = blockIdx.x * 256 + threadIdx.x;
    if (i >= n) return;
    float x = w[i];
    __nv_bfloat16 h = __float2bfloat16(x);
    hi[i] = h;
    lo[i] = __float2bfloat16(x - __bfloat162float(h));
}

// ---------------------------------------------------------------------------
// Init: zero encoder states (fp32 + hi/lo), load initial tokens
// ---------------------------------------------------------------------------
__global__ void init_kernel(const int* __restrict__ tgt)
{
    int i = blockIdx.x * 256 + threadIdx.x;   // < 2*512*1024 = 1048576
    if (i < 2 * Bq * Hq) {
        (&g_h_e[0][0][0])[i] = 0.f;
        (&g_hhi_e[0][0][0])[i] = __float2bfloat16(0.f);
        (&g_hlo_e[0][0][0])[i] = __float2bfloat16(0.f);
    }
    if (i < Bq) g_tok[i] = tgt[i * Tq + 0];
}

// ---------------------------------------------------------------------------
// Tensor-core (mma.sync bf16x3) GEMM: gh[M,Ntot] = A[M,K] @ W[Ntot,K]^T
// mode 0: encoder (blockIdx.z = dir, K=1024, Ntot=3072)
// mode 1: decoder (K=2048, Ntot=6144)
// CTA tile 128x128, K-chunk 64, cp.async double buffer, 8 warps (64x32 each).
// SMEM buffer layout (64KB): Ah | Al | Bh | Bl, each 128 rows x 128 bytes,
// XOR-swizzled 16B units for conflict-free ldmatrix.
// ---------------------------------------------------------------------------
#define GEMM_SMEM_BYTES (2 * 65536 + 1024)

__global__ __launch_bounds__(256, 1) void gemm_mma_kernel(int mode)
{
    extern __shared__ char smraw[];
    u32 raw = smem_u32(smraw);
    u32 base = (raw + 1023) & ~1023u;

    int tid = threadIdx.x;
    int wid = tid >> 5;
    int lane = tid & 31;

    int K, Ntot, NC;
    const __nv_bfloat16 *Ah, *Al, *Bh, *Bl;
    float* out;
    if (mode == 0) {
        int dir = blockIdx.z;
        K = Hq; Ntot = G3H; NC = Hq / 64;
        Ah = &g_hhi_e[dir][0][0]; Al = &g_hlo_e[dir][0][0];
        Bh = &g_Whi_e[dir][0][0]; Bl = &g_Wlo_e[dir][0][0];
        out = &g_gh_e[dir][0][0];
    } else {
        K = H2q; Ntot = G6H; NC = H2q / 64;
        Ah = &g_hhi_d[0][0]; Al = &g_hlo_d[0][0];
        Bh = &g_Whi_d[0][0]; Bl = &g_Wlo_d[0][0];
        out = &g_gh_d[0][0];
    }

    int bm = blockIdx.y * 128, bn = blockIdx.x * 128;
    const __nv_bfloat16* pAh = Ah + (size_t)bm * K;
    const __nv_bfloat16* pAl = Al + (size_t)bm * K;
    const __nv_bfloat16* pBh = Bh + (size_t)bn * K;
    const __nv_bfloat16* pBl = Bl + (size_t)bn * K;

    // staging coords: 4 x 16B per sub-tile per thread
    u32 soff[4];
    size_t goff[4];
    #pragma unroll
    for (int p = 0; p < 4; p++) {
        int u = tid + 256 * p;
        int row = u >> 3, c = u & 7;
        goff[p] = (size_t)row * K + c * 8;            // elements; + chunk*64 later
        soff[p] = swz(row * 128 + c * 16);
    }

    // warp tile
    int m0 = (wid >> 2) * 64;
    int n0 = (wid & 3) * 32;

    float acc[4][4][4];   // [matom][natom][4]
    #pragma unroll
    for (int i = 0; i < 4; i++)
        #pragma unroll
        for (int n = 0; n < 4; n++)
            #pragma unroll
            for (int q = 0; q < 4; q++) acc[i][n][q] = 0.f;

    // prologue: stage chunk 0 -> buffer 0
    #pragma unroll
    for (int p = 0; p < 4; p++) {
        u32 s0 = base + soff[p];
        cp16(s0 + 0,     pAh + goff[p]);
        cp16(s0 + 16384, pAl + goff[p]);
        cp16(s0 + 32768, pBh + goff[p]);
        cp16(s0 + 49152, pBl + goff[p]);
    }
    cp_commit();

    for (int c = 0; c < NC; c++) {
        int s = c & 1;
        __syncthreads();   // all warps done reading buffer s^1 (prev compute)
        if (c + 1 < NC) {
            size_t kb = (size_t)(c + 1) * 64;
            u32 bnext = base + (s ^ 1) * 65536;
            #pragma unroll
            for (int p = 0; p < 4; p++) {
                u32 s0 = bnext + soff[p];
                cp16(s0 + 0,     pAh + goff[p] + kb);
                cp16(s0 + 16384, pAl + goff[p] + kb);
                cp16(s0 + 32768, pBh + goff[p] + kb);
                cp16(s0 + 49152, pBl + goff[p] + kb);
            }
            cp_commit();
            cp_wait1();    // buffer s loads complete
        } else {
            cp_wait0();
        }
        __syncthreads();

        u32 buf = base + s * 65536;
        int arow = lane & 15;
        int acol = (lane >> 4) * 16;

        #pragma unroll
        for (int ks = 0; ks < 4; ks++) {
            int obyte = ks * 32 + acol;
            u32 af[2][4][4];   // [split][matom][4]
            u32 bf[2][2][4];   // [split][npair][4]
            #pragma unroll
            for (int i = 0; i < 4; i++) {
                u32 off = swz((m0 + i * 16 + arow) * 128 + obyte);
                ldsm4(buf + off,         af[0][i][0], af[0][i][1], af[0][i][2], af[0][i][3]);
                ldsm4(buf + 16384 + off, af[1][i][0], af[1][i][1], af[1][i][2], af[1][i][3]);
            }
            #pragma unroll
            for (int j = 0; j < 2; j++) {
                u32 off = swz((n0 + j * 16 + arow) * 128 + obyte);
                ldsm4(buf + 32768 + off, bf[0][j][0], bf[0][j][1], bf[0][j][2], bf[0][j][3]);
                ldsm4(buf + 49152 + off, bf[1][j][0], bf[1][j][1], bf[1][j][2], bf[1][j][3]);
            }
            #pragma unroll
            for (int i = 0; i < 4; i++) {
                #pragma unroll
                for (int j = 0; j < 2; j++) {
                    #pragma unroll
                    for (int q = 0; q < 2; q++) {
                        int n = j * 2 + q;
                        // hi*hi
                        mma16816(acc[i][n], af[0][i], bf[0][j][q], bf[0][j][q + 2]);
                        // hi*lo
                        mma16816(acc[i][n], af[0][i], bf[1][j][q], bf[1][j][q + 2]);
                        // lo*hi
                        mma16816(acc[i][n], af[1][i], bf[0][j][q], bf[0][j][q + 2]);
                    }
                }
            }
        }
    }

    // epilogue: write fp32 gh
    int g = lane >> 2, tig = lane & 3;
    #pragma unroll
    for (int i = 0; i < 4; i++) {
        int row0 = bm + m0 + i * 16 + g;
        #pragma unroll
        for (int n = 0; n < 4; n++) {
            int col = bn + n0 + n * 8 + tig * 2;
            *(float2*)(out + (size_t)row0 * Ntot + col)       = make_float2(acc[i][n][0], acc[i][n][1]);
            *(float2*)(out + (size_t)(row0 + 8) * Ntot + col) = make_float2(acc[i][n][2], acc[i][n][3]);
        }
    }
}

// ---------------------------------------------------------------------------
// Encoder GRU update: h' = (1-z)*n + z*h from gh + gi table; writes fp32 + hi/lo
// ---------------------------------------------------------------------------
__device__ __forceinline__ unsigned pack_bf2(float a, float b) {
    __nv_bfloat162 p = __floats2bfloat162_rn(a, b);
    return *(unsigned*)&p;
}

__global__ __launch_bounds__(256) void enc_update_kernel(
    const int* __restrict__ src,
    const float* __restrict__ bhf, const float* __restrict__ bhb, int t)
{
    int i = blockIdx.x * 256 + threadIdx.x;    // 0..262143
    int dir = i >> 17;
    int r = i & 131071;
    int b = r >> 8;
    int n = (r & 255) * 4;
    const float* bh = dir ? bhb : bhf;
    int s = dir ? (Sq - 1 - t) : t;
    int tok = src[b * Sq + s];

    const float* gh = &g_gh_e[dir][b][0];
    const float* gi = &g_encA[dir][tok][0];
    float* hp = &g_h_e[dir][b][0];

    float4 ghr = *(const float4*)(gh + n);
    float4 ghz = *(const float4*)(gh + Hq + n);
    float4 ghn = *(const float4*)(gh + 2 * Hq + n);
    float4 gir = *(const float4*)(gi + n);
    float4 giz = *(const float4*)(gi + Hq + n);
    float4 gin = *(const float4*)(gi + 2 * Hq + n);
    float4 bhr = *(const float4*)(bh + n);
    float4 bhz = *(const float4*)(bh + Hq + n);
    float4 bhn = *(const float4*)(bh + 2 * Hq + n);
    float4 h4  = *(const float4*)(hp + n);

    float hr[4] = {ghr.x+bhr.x, ghr.y+bhr.y, ghr.z+bhr.z, ghr.w+bhr.w};
    float hz[4] = {ghz.x+bhz.x, ghz.y+bhz.y, ghz.z+bhz.z, ghz.w+bhz.w};
    float hn[4] = {ghn.x+bhn.x, ghn.y+bhn.y, ghn.z+bhn.z, ghn.w+bhn.w};
    float ir[4] = {gir.x, gir.y, gir.z, gir.w};
    float iz[4] = {giz.x, giz.y, giz.z, giz.w};
    float in_[4]= {gin.x, gin.y, gin.z, gin.w};
    float hv[4] = {h4.x, h4.y, h4.z, h4.w};
    float ho[4];
    #pragma unroll
    for (int q = 0; q < 4; q++) {
        float rr = sigf(ir[q] + hr[q]);
        float zz = sigf(iz[q] + hz[q]);
        float nn = tanhf(in_[q] + rr * hn[q]);
        ho[q] = (1.f - zz) * nn + zz * hv[q];
    }
    *(float4*)(hp + n) = make_float4(ho[0], ho[1], ho[2], ho[3]);

    float hi[4], lo[4];
    #pragma unroll
    for (int q = 0; q < 4; q++) {
        __nv_bfloat16 h = __float2bfloat16(ho[q]);
        hi[q] = __bfloat162float(h);
        lo[q] = ho[q] - hi[q];
    }
    uint2 vh, vl;
    vh.x = pack_bf2(hi[0], hi[1]); vh.y = pack_bf2(hi[2], hi[3]);
    vl.x = pack_bf2(lo[0], lo[1]); vl.y = pack_bf2(lo[2], lo[3]);
    *(uint2*)&g_hhi_e[dir][b][n] = vh;
    *(uint2*)&g_hlo_e[dir][b][n] = vl;
}

// ---------------------------------------------------------------------------
// Concat encoder final states -> decoder h0 (fp32 + hi/lo)
// ---------------------------------------------------------------------------
__global__ void concat_kernel()
{
    int i = blockIdx.x * 256 + threadIdx.x;  // < 512*2048
    int b = i >> 11, j = i & 2047;
    float v = (j < Hq) ? g_h_e[0][b][j] : g_h_e[1][b][j - Hq];
    g_hdec_f[b][j] = v;
    __nv_bfloat16 h = __float2bfloat16(v);
    g_hhi_d[b][j] = h;
    g_hlo_d[b][j] = __float2bfloat16(v - __bfloat162float(h));
}

// ---------------------------------------------------------------------------
// Decoder GRU update
// ---------------------------------------------------------------------------
__global__ __launch_bounds__(256) void dec_update_kernel(const float* __restrict__ bhd)
{
    int i = blockIdx.x * 256 + threadIdx.x;    // 0..262143
    int b = i >> 9;
    int n = (i & 511) * 4;
    int tok = g_tok[b];

    const float* gh = &g_gh_d[b][0];
    const float* gi = &g_decA[tok][0];
    float* hp = &g_hdec_f[b][0];

    float4 ghr = *(const float4*)(gh + n);
    float4 ghz = *(const float4*)(gh + H2q + n);
    float4 ghn = *(const float4*)(gh + 2 * H2q + n);
    float4 gir = *(const float4*)(gi + n);
    float4 giz = *(const float4*)(gi + H2q + n);
    float4 gin = *(const float4*)(gi + 2 * H2q + n);
    float4 bhr = *(const float4*)(bhd + n);
    float4 bhz = *(const float4*)(bhd + H2q + n);
    float4 bhn = *(const float4*)(bhd + 2 * H2q + n);
    float4 h4  = *(const float4*)(hp + n);

    float hr[4] = {ghr.x+bhr.x, ghr.y+bhr.y, ghr.z+bhr.z, ghr.w+bhr.w};
    float hz[4] = {ghz.x+bhz.x, ghz.y+bhz.y, ghz.z+bhz.z, ghz.w+bhz.w};
    float hn[4] = {ghn.x+bhn.x, ghn.y+bhn.y, ghn.z+bhn.z, ghn.w+bhn.w};
    float ir[4] = {gir.x, gir.y, gir.z, gir.w};
    float iz[4] = {giz.x, giz.y, giz.z, giz.w};
    float in_[4]= {gin.x, gin.y, gin.z, gin.w};
    float hv[4] = {h4.x, h4.y, h4.z, h4.w};
    float ho[4];
    #pragma unroll
    for (int q = 0; q < 4; q++) {
        float rr = sigf(ir[q] + hr[q]);
        float zz = sigf(iz[q] + hz[q]);
        float nn = tanhf(in_[q] + rr * hn[q]);
        ho[q] = (1.f - zz) * nn + zz * hv[q];
    }
    *(float4*)(hp + n) = make_float4(ho[0], ho[1], ho[2], ho[3]);

    float hi[4], lo[4];
    #pragma unroll
    for (int q = 0; q < 4; q++) {
        __nv_bfloat16 h = __float2bfloat16(ho[q]);
        hi[q] = __bfloat162float(h);
        lo[q] = ho[q] - hi[q];
    }
    uint2 vh, vl;
    vh.x = pack_bf2(hi[0], hi[1]); vh.y = pack_bf2(hi[2], hi[3]);
    vl.x = pack_bf2(lo[0], lo[1]); vl.y = pack_bf2(lo[2], lo[3]);
    *(uint2*)&g_hhi_d[b][n] = vh;
    *(uint2*)&g_hlo_d[b][n] = vl;
}

// ---------------------------------------------------------------------------
// Logits partials: K-split (x8) of h_new[512,2048] @ W_fc[128,2048]^T  (fp32)
// ---------------------------------------------------------------------------
__global__ __launch_bounds__(256) void logits_part_kernel(const float* __restrict__ Wfc)
{
    const int K = H2q;
    const float* h = &g_hdec_f[0][0];
    int ks = blockIdx.x;
    int bm = blockIdx.y * 64;
    int kb = ks * 256;

    __shared__ float As[16][68];
    __shared__ float Bs[16][132];

    int tid = threadIdx.x;
    int tx = tid & 15, ty = tid >> 4;
    int lr = tid >> 2, lc = tid & 3;
    int wr = tid >> 1, wc = (tid & 1) * 8;

    float acc[4][8];
    #pragma unroll
    for (int i = 0; i < 4; i++)
        #pragma unroll
        for (int j = 0; j < 8; j++) acc[i][j] = 0.f;

    const float* Arow = h + (bm + lr) * K + kb + lc * 4;
    const float* Wrow = Wfc + wr * K + kb + wc;

    for (int k0 = 0; k0 < 256; k0 += 16) {
        float4 a4 = *(const float4*)(Arow + k0);
        float4 u0 = *(const float4*)(Wrow + k0);
        float4 u1 = *(const float4*)(Wrow + k0 + 4);
        As[lc*4+0][lr] = a4.x; As[lc*4+1][lr] = a4.y; As[lc*4+2][lr] = a4.z; As[lc*4+3][lr] = a4.w;
        Bs[wc+0][wr] = u0.x; Bs[wc+1][wr] = u0.y; Bs[wc+2][wr] = u0.z; Bs[wc+3][wr] = u0.w;
        Bs[wc+4][wr] = u1.x; Bs[wc+5][wr] = u1.y; Bs[wc+6][wr] = u1.z; Bs[wc+7][wr] = u1.w;
        __syncthreads();
        #pragma unroll
        for (int k = 0; k < 16; k++) {
            float4 av = *(const float4*)&As[k][ty * 4];
            float4 b0 = *(const float4*)&Bs[k][tx * 8];
            float4 b1 = *(const float4*)&Bs[k][tx * 8 + 4];
            float am[4] = {av.x, av.y, av.z, av.w};
            float v[8]  = {b0.x, b0.y, b0.z, b0.w, b1.x, b1.y, b1.z, b1.w};
            #pragma unroll
            for (int i = 0; i < 4; i++)
                #pragma unroll
                for (int j = 0; j < 8; j++) acc[i][j] += am[i] * v[j];
        }
        __syncthreads();
    }

    #pragma unroll
    for (int i = 0; i < 4; i++)
        #pragma unroll
        for (int j = 0; j < 8; j++)
            g_lpart[ks][bm + ty * 4 + i][tx * 8 + j] = acc[i][j];
}

// ---------------------------------------------------------------------------
// Reduce partials + bias, write logits, argmax -> g_tok
// ---------------------------------------------------------------------------
__global__ __launch_bounds__(128) void reduce_argmax_kernel(
    const float* __restrict__ bfc, float* __restrict__ out, int t)
{
    int b = blockIdx.x;
    int v = threadIdx.x;
    float s = bfc[v];
    #pragma unroll
    for (int ks = 0; ks < 8; ks++) s += g_lpart[ks][b][v];
    out[((size_t)b * (Tq - 1) + t) * Vq + v] = s;

    __shared__ float sv[128];
    __shared__ int   si[128];
    sv[v] = s; si[v] = v;
    __syncthreads();
    #pragma unroll
    for (int off = 64; off > 0; off >>= 1) {
        if (v < off) {
            float o = sv[v + off]; int oi = si[v + off];
            if (o > sv[v] || (o == sv[v] && oi < si[v])) { sv[v] = o; si[v] = oi; }
        }
        __syncthreads();
    }
    if (v == 0) g_tok[b] = si[0];
}

// ---------------------------------------------------------------------------
extern "C" void kernel_launch(void* const* d_in, const int* in_sizes, int n_in,
                              void* d_out, int out_size)
{
    const int*   src     = (const int*)d_in[0];
    const int*   tgt     = (const int*)d_in[1];
    const float* enc_emb = (const float*)d_in[2];
    const float* dec_emb = (const float*)d_in[3];
    const float* W_ih_f  = (const float*)d_in[4];
    const float* W_hh_f  = (const float*)d_in[5];
    const float* b_ih_f  = (const float*)d_in[6];
    const float* b_hh_f  = (const float*)d_in[7];
    const float* W_ih_b  = (const float*)d_in[8];
    const float* W_hh_b  = (const float*)d_in[9];
    const float* b_ih_b  = (const float*)d_in[10];
    const float* b_hh_b  = (const float*)d_in[11];
    const float* W_ih_d  = (const float*)d_in[12];
    const float* W_hh_d  = (const float*)d_in[13];
    const float* b_ih_d  = (const float*)d_in[14];
    const float* b_hh_d  = (const float*)d_in[15];
    const float* W_fc    = (const float*)d_in[16];
    const float* b_fc    = (const float*)d_in[17];
    float* out = (float*)d_out;

    static int attr_set = 0;
    if (!attr_set) {
        cudaFuncSetAttribute(gemm_mma_kernel,
                             cudaFuncAttributeMaxDynamicSharedMemorySize, GEMM_SMEM_BYTES);
        attr_set = 1;
    }

    // device symbol addresses for weight split outputs
    __nv_bfloat16 *whi_e0, *wlo_e0, *whi_e1, *wlo_e1, *whi_d, *wlo_d;
    cudaGetSymbolAddress((void**)&whi_e0, g_Whi_e);
    cudaGetSymbolAddress((void**)&wlo_e0, g_Wlo_e);
    cudaGetSymbolAddress((void**)&whi_d,  g_Whi_d);
    cudaGetSymbolAddress((void**)&wlo_d,  g_Wlo_d);
    whi_e1 = whi_e0 + (size_t)G3H * Hq;
    wlo_e1 = wlo_e0 + (size_t)G3H * Hq;

    // Weight hi/lo split (recurrent matrices)
    {
        int n1 = G3H * Hq;           // 3.1M
        int n2 = G6H * H2q;          // 12.6M
        wsplit_kernel<<<(n1 + 255) / 256, 256>>>(W_hh_f, whi_e0, wlo_e0, n1);
        wsplit_kernel<<<(n1 + 255) / 256, 256>>>(W_hh_b, whi_e1, wlo_e1, n1);
        wsplit_kernel<<<(n2 + 255) / 256, 256>>>(W_hh_d, whi_d, wlo_d, n2);
    }

    // Projection tables (input GEMMs collapse to 128-row tables)
    table_kernel<<<dim3(96, 2, 3), 256>>>(enc_emb, dec_emb,
                                          W_ih_f, b_ih_f, W_ih_b, b_ih_b, W_ih_d, b_ih_d);
    // h0 = 0, tok0 = tgt[:,0]
    init_kernel<<<4096, 256>>>(tgt);

    // Bidirectional encoder: tensor-core GEMM + elementwise GRU update
    for (int t = 0; t < Sq; t++) {
        gemm_mma_kernel<<<dim3(24, 4, 2), 256, GEMM_SMEM_BYTES>>>(0);
        enc_update_kernel<<<1024, 256>>>(src, b_hh_f, b_hh_b, t);
    }

    // decoder h0 = concat(h_fwd, h_bwd)
    concat_kernel<<<4096, 256>>>();

    // Greedy decoder
    for (int t = 0; t < Tq - 1; t++) {
        gemm_mma_kernel<<<dim3(48, 4, 1), 256, GEMM_SMEM_BYTES>>>(1);
        dec_update_kernel<<<1024, 256>>>(b_hh_d);
        logits_part_kernel<<<dim3(8, 8), 256>>>(W_fc);
        reduce_argmax_kernel<<<Bq, 128>>>(b_fc, out, t);
    }
}

// round 10
// speedup vs baseline: 2.1562x; 1.1986x over previous
#include <cuda_runtime.h>
#include <cuda_bf16.h>
#include <math.h>

// Problem dims
#define Bq   512
#define Sq   64
#define Tq   32
#define Eq   512
#define Hq   1024
#define H2q  2048
#define G3H  3072   // 3*H
#define G6H  6144   // 3*2H
#define Vq   128

typedef unsigned long long u64;
typedef unsigned int u32;

// ---------------------------------------------------------------------------
// Scratch (device statics; allocation-free)
// Weight/table/bias arrays live in gate-grouped PERMUTED layout:
//   original row (g*H + j)  ->  permuted row (j/64)*192 + g*64 + (j%64)
// so one 192-wide N-tile = complete r/z/n triples for 64 h-columns.
// ---------------------------------------------------------------------------
__device__ float g_encA[2][Vq][G3H];        // gi tables (permuted, incl b_ih)
__device__ float g_decA[Vq][G6H];           // decoder gi table (permuted)
__device__ float g_bhe[2][G3H];             // b_hh enc (permuted)
__device__ float g_bhd[G6H];                // b_hh dec (permuted)
__device__ float g_lpart[16][Bq][Vq];       // logits K-split partials
__device__ int   g_tok[Bq];                 // current decoder tokens

// hidden states (ping-pong)
__device__ float g_h_e[2][2][Bq][Hq];                 // [dir][pp][b][h]
__device__ float g_hdec_f[2][Bq][H2q];                // [pp][b][2h]
__device__ __nv_bfloat16 g_hhi_e[2][2][Bq][Hq], g_hlo_e[2][2][Bq][Hq];
__device__ __nv_bfloat16 g_hhi_d[2][Bq][H2q],   g_hlo_d[2][Bq][H2q];

// bf16 hi/lo split weights (recurrent: permuted; fc: natural)
__device__ __nv_bfloat16 g_Whi_e[2][G3H][Hq], g_Wlo_e[2][G3H][Hq];
__device__ __nv_bfloat16 g_Whi_d[G6H][H2q],   g_Wlo_d[G6H][H2q];
__device__ __nv_bfloat16 g_Wfc_hi[Vq][H2q],   g_Wfc_lo[Vq][H2q];

// ---------------------------------------------------------------------------
// Helpers
// ---------------------------------------------------------------------------
__device__ __forceinline__ float sigf(float x) { return 1.0f / (1.0f + expf(-x)); }

__device__ __forceinline__ u32 smem_u32(const void* p) {
    u32 a;
    asm("{ .reg .u64 t; cvta.to.shared.u64 t, %1; cvt.u32.u64 %0, t; }" : "=r"(a) : "l"(p));
    return a;
}
__device__ __forceinline__ u32 swz(u32 o) { return o ^ ((o >> 3) & 0x70); }

__device__ __forceinline__ void cp16(u32 saddr, const void* gaddr) {
    asm volatile("cp.async.cg.shared.global [%0], [%1], 16;" :: "r"(saddr), "l"(gaddr) : "memory");
}
__device__ __forceinline__ void cp_commit() {
    asm volatile("cp.async.commit_group;" ::: "memory");
}
__device__ __forceinline__ void cp_wait1() {
    asm volatile("cp.async.wait_group 1;" ::: "memory");
}
__device__ __forceinline__ void cp_wait0() {
    asm volatile("cp.async.wait_group 0;" ::: "memory");
}
__device__ __forceinline__ void ldsm4(u32 addr, u32& r0, u32& r1, u32& r2, u32& r3) {
    asm volatile("ldmatrix.sync.aligned.m8n8.x4.shared.b16 {%0,%1,%2,%3}, [%4];"
                 : "=r"(r0), "=r"(r1), "=r"(r2), "=r"(r3) : "r"(addr));
}
__device__ __forceinline__ void mma16816(float* c, const u32* a, u32 b0, u32 b1) {
    asm volatile(
        "mma.sync.aligned.m16n8k16.row.col.f32.bf16.bf16.f32 "
        "{%0,%1,%2,%3}, {%4,%5,%6,%7}, {%8,%9}, {%0,%1,%2,%3};"
        : "+f"(c[0]), "+f"(c[1]), "+f"(c[2]), "+f"(c[3])
        : "r"(a[0]), "r"(a[1]), "r"(a[2]), "r"(a[3]), "r"(b0), "r"(b1));
}

// ---------------------------------------------------------------------------
// Projection tables: C[M=128, N] = A[128,512] @ W[N,512]^T + bias[N]
// writes PERMUTED (gate-grouped) layout
// ---------------------------------------------------------------------------
__global__ __launch_bounds__(256) void table_kernel(
    const float* __restrict__ enc_emb, const float* __restrict__ dec_emb,
    const float* __restrict__ Wf, const float* __restrict__ bf,
    const float* __restrict__ Wb, const float* __restrict__ bb,
    const float* __restrict__ Wd, const float* __restrict__ bd)
{
    int z = blockIdx.z;
    const float* A; const float* W; const float* bias; float* out; int N; int H;
    if (z == 0)      { A = enc_emb; W = Wf; bias = bf; out = &g_encA[0][0][0]; N = G3H; H = Hq; }
    else if (z == 1) { A = enc_emb; W = Wb; bias = bb; out = &g_encA[1][0][0]; N = G3H; H = Hq; }
    else             { A = dec_emb; W = Wd; bias = bd; out = &g_decA[0][0];    N = G6H; H = H2q; }

    int bn = blockIdx.x * 64;
    if (bn >= N) return;
    int bm = blockIdx.y * 64;
    const int K = Eq;

    __shared__ float As[16][68];
    __shared__ float Bs[16][68];

    int tid = threadIdx.x;
    int tx = tid & 15, ty = tid >> 4;
    int lr = tid >> 2, lc = tid & 3;

    float acc[4][4];
    #pragma unroll
    for (int i = 0; i < 4; i++)
        #pragma unroll
        for (int j = 0; j < 4; j++) acc[i][j] = 0.f;

    for (int k0 = 0; k0 < K; k0 += 16) {
        float4 a4 = *(const float4*)&A[(bm + lr) * K + k0 + lc * 4];
        float4 w4 = *(const float4*)&W[(bn + lr) * K + k0 + lc * 4];
        As[lc*4+0][lr] = a4.x; As[lc*4+1][lr] = a4.y; As[lc*4+2][lr] = a4.z; As[lc*4+3][lr] = a4.w;
        Bs[lc*4+0][lr] = w4.x; Bs[lc*4+1][lr] = w4.y; Bs[lc*4+2][lr] = w4.z; Bs[lc*4+3][lr] = w4.w;
        __syncthreads();
        #pragma unroll
        for (int k = 0; k < 16; k++) {
            float4 av = *(const float4*)&As[k][ty * 4];
            float4 bv = *(const float4*)&Bs[k][tx * 4];
            float am[4] = {av.x, av.y, av.z, av.w};
            float bm4[4] = {bv.x, bv.y, bv.z, bv.w};
            #pragma unroll
            for (int i = 0; i < 4; i++)
                #pragma unroll
                for (int j = 0; j < 4; j++) acc[i][j] += am[i] * bm4[j];
        }
        __syncthreads();
    }

    #pragma unroll
    for (int i = 0; i < 4; i++) {
        int m = bm + ty * 4 + i;
        #pragma unroll
        for (int j = 0; j < 4; j++) {
            int n = bn + tx * 4 + j;
            int g = n / H, jj = n % H;
            int pn = (jj >> 6) * 192 + g * 64 + (jj & 63);
            out[m * N + pn] = acc[i][j] + bias[n];
        }
    }
}

// ---------------------------------------------------------------------------
// Weight splits
// ---------------------------------------------------------------------------
__global__ void wsplit_kernel(const float* __restrict__ w,
                              __nv_bfloat16* __restrict__ hi,
                              __nv_bfloat16* __restrict__ lo, int n)
{
    int i = blockIdx.x * 256 + threadIdx.x;
    if (i >= n) return;
    float x = w[i];
    __nv_bfloat16 h = __float2bfloat16(x);
    hi[i] = h;
    lo[i] = __float2bfloat16(x - __bfloat162float(h));
}

// permuted split for recurrent weights [3H, K]
__global__ void wsplit_perm_kernel(const float* __restrict__ w,
                                   __nv_bfloat16* __restrict__ hi,
                                   __nv_bfloat16* __restrict__ lo,
                                   int H, int K, int n)
{
    int i = blockIdx.x * 256 + threadIdx.x;
    if (i >= n) return;
    int row = i / K, col = i % K;
    int g = row / H, jj = row % H;
    int prow = (jj >> 6) * 192 + g * 64 + (jj & 63);
    float x = w[i];
    __nv_bfloat16 h = __float2bfloat16(x);
    size_t o = (size_t)prow * K + col;
    hi[o] = h;
    lo[o] = __float2bfloat16(x - __bfloat162float(h));
}

// permute b_hh vectors
__global__ void bperm_kernel(const float* __restrict__ bf,
                             const float* __restrict__ bb,
                             const float* __restrict__ bd)
{
    int i = blockIdx.x * 256 + threadIdx.x;
    if (i < 2 * G3H) {
        int d = i / G3H, n = i % G3H;
        int g = n / Hq, jj = n % Hq;
        g_bhe[d][(jj >> 6) * 192 + g * 64 + (jj & 63)] = d ? bb[n] : bf[n];
    }
    if (i < G6H) {
        int g = i / H2q, jj = i % H2q;
        g_bhd[(jj >> 6) * 192 + g * 64 + (jj & 63)] = bd[i];
    }
}

// ---------------------------------------------------------------------------
// Init: zero encoder ping-0 states, load initial tokens
// ---------------------------------------------------------------------------
__global__ void init_kernel(const int* __restrict__ tgt)
{
    int i = blockIdx.x * 256 + threadIdx.x;   // < 2*512*1024
    if (i < 2 * Bq * Hq) {
        int d = i / (Bq * Hq), off = i % (Bq * Hq);
        (&g_h_e[d][0][0][0])[off] = 0.f;
        (&g_hhi_e[d][0][0][0])[off] = __float2bfloat16(0.f);
        (&g_hlo_e[d][0][0][0])[off] = __float2bfloat16(0.f);
    }
    if (i < Bq) g_tok[i] = tgt[i * Tq + 0];
}

// ---------------------------------------------------------------------------
// Fused GRU step: gh = h @ Wperm^T (bf16x3 mma), then GRU update in epilogue.
// mode 0: encoder (z=dir, K=1024, Ntot=3072, grid 16x4x2 = 128 CTAs)
// mode 1: decoder (K=2048, Ntot=6144, grid 32x4x1 = 128 CTAs)
// CTA tile 128x192, K-chunk 64 double-buffered cp.async.
// SMEM stage: Ahi(16K)|Alo(16K)|Bhi(24K)|Blo(24K) = 80KB, x2 = 160KB.
// Epilogue: acc -> smem (128x196 f32), gate triples recombined per thread.
// ---------------------------------------------------------------------------
#define STGB 81920
#define GEMM_SMEM (2 * STGB + 1024)
#define LDE 196

__global__ __launch_bounds__(256, 1) void gru_step_kernel(int mode, int t,
                                                          const int* __restrict__ src)
{
    extern __shared__ char smraw[];
    u32 raw = smem_u32(smraw);
    u32 base = (raw + 1023) & ~1023u;

    int tid = threadIdx.x, wid = tid >> 5, lane = tid & 31;
    int bx = blockIdx.x, bm = blockIdx.y * 128;

    int K, Ntot, dir = 0;
    const __nv_bfloat16 *pAh, *pAl, *pBh, *pBl;
    const float *tab, *bh, *hprevf;
    float* houtf; __nv_bfloat16 *houthi, *houtlo;
    if (mode == 0) {
        dir = blockIdx.z;
        K = Hq; Ntot = G3H;
        int pp = t & 1, pn = pp ^ 1;
        pAh = &g_hhi_e[dir][pp][0][0]; pAl = &g_hlo_e[dir][pp][0][0];
        pBh = &g_Whi_e[dir][0][0];     pBl = &g_Wlo_e[dir][0][0];
        tab = &g_encA[dir][0][0];      bh  = &g_bhe[dir][0];
        hprevf = &g_h_e[dir][pp][0][0];
        houtf  = &g_h_e[dir][pn][0][0];
        houthi = &g_hhi_e[dir][pn][0][0]; houtlo = &g_hlo_e[dir][pn][0][0];
    } else {
        K = H2q; Ntot = G6H;
        int pp = t & 1, pn = pp ^ 1;
        pAh = &g_hhi_d[pp][0][0]; pAl = &g_hlo_d[pp][0][0];
        pBh = &g_Whi_d[0][0];     pBl = &g_Wlo_d[0][0];
        tab = &g_decA[0][0];      bh  = &g_bhd[0];
        hprevf = &g_hdec_f[pp][0][0];
        houtf  = &g_hdec_f[pn][0][0];
        houthi = &g_hhi_d[pn][0][0]; houtlo = &g_hlo_d[pn][0][0];
    }
    const int Hloc = K;          // h width == K for both modes
    const int NC = K / 64;
    int bn = bx * 192;
    pAh += (size_t)bm * K; pAl += (size_t)bm * K;
    pBh += (size_t)bn * K; pBl += (size_t)bn * K;

    // warp tile: 2x4 grid of 64x48
    int m0 = (wid >> 2) * 64;
    int n0 = (wid & 3) * 48;

    float acc[4][6][4];
    #pragma unroll
    for (int i = 0; i < 4; i++)
        #pragma unroll
        for (int n = 0; n < 6; n++)
            #pragma unroll
            for (int q = 0; q < 4; q++) acc[i][n][q] = 0.f;

    // ---- staging (per chunk: A 256 rows of 128B, B 384 rows of 128B) ----
    #define STAGE(stg, kb) do {                                              \
        u32 sb_ = base + (stg) * STGB;                                       \
        _Pragma("unroll")                                                    \
        for (int p = 0; p < 8; p++) {                                        \
            int u_ = tid + 256 * p; int row_ = u_ >> 3, c_ = u_ & 7;         \
            int r_ = row_ & 127;                                             \
            const __nv_bfloat16* g_ = (row_ < 128 ? pAh : pAl)               \
                                      + (size_t)r_ * K + (kb) + c_ * 8;      \
            cp16(sb_ + (row_ < 128 ? 0u : 16384u) + swz(r_ * 128 + c_ * 16), g_); \
        }                                                                    \
        _Pragma("unroll")                                                    \
        for (int p = 0; p < 12; p++) {                                       \
            int u_ = tid + 256 * p; int row_ = u_ >> 3, c_ = u_ & 7;         \
            int r_ = (row_ < 192) ? row_ : row_ - 192;                       \
            const __nv_bfloat16* g_ = (row_ < 192 ? pBh : pBl)               \
                                      + (size_t)r_ * K + (kb) + c_ * 8;      \
            cp16(sb_ + (row_ < 192 ? 32768u : 57344u) + swz(r_ * 128 + c_ * 16), g_); \
        }                                                                    \
    } while (0)

    STAGE(0, 0);
    cp_commit();

    for (int c = 0; c < NC; c++) {
        int s = c & 1;
        __syncthreads();
        if (c + 1 < NC) {
            STAGE(s ^ 1, (size_t)(c + 1) * 64);
            cp_commit();
            cp_wait1();
        } else {
            cp_wait0();
        }
        __syncthreads();

        u32 buf = base + s * STGB;
        int arow = lane & 15;
        int acol = (lane >> 4) * 16;

        #pragma unroll
        for (int ks = 0; ks < 4; ks++) {
            int obyte = ks * 32 + acol;
            u32 af[2][4][4];
            u32 bf[2][3][4];
            #pragma unroll
            for (int i = 0; i < 4; i++) {
                u32 off = swz((m0 + i * 16 + arow) * 128 + obyte);
                ldsm4(buf + off,          af[0][i][0], af[0][i][1], af[0][i][2], af[0][i][3]);
                ldsm4(buf + 16384 + off,  af[1][i][0], af[1][i][1], af[1][i][2], af[1][i][3]);
            }
            #pragma unroll
            for (int j = 0; j < 3; j++) {
                u32 off = swz((n0 + j * 16 + arow) * 128 + obyte);
                ldsm4(buf + 32768 + off,  bf[0][j][0], bf[0][j][1], bf[0][j][2], bf[0][j][3]);
                ldsm4(buf + 57344 + off,  bf[1][j][0], bf[1][j][1], bf[1][j][2], bf[1][j][3]);
            }
            #pragma unroll
            for (int i = 0; i < 4; i++) {
                #pragma unroll
                for (int j = 0; j < 3; j++) {
                    #pragma unroll
                    for (int q = 0; q < 2; q++) {
                        int n = j * 2 + q;
                        mma16816(acc[i][n], af[0][i], bf[0][j][q], bf[0][j][q + 2]);
                        mma16816(acc[i][n], af[0][i], bf[1][j][q], bf[1][j][q + 2]);
                        mma16816(acc[i][n], af[1][i], bf[0][j][q], bf[0][j][q + 2]);
                    }
                }
            }
        }
    }

    // ---- epilogue: acc -> smem, recombine gate triples, GRU update ----
    __syncthreads();
    float* smf = (float*)smraw;
    {
        int g = lane >> 2, tig = lane & 3;
        #pragma unroll
        for (int i = 0; i < 4; i++) {
            int row = m0 + i * 16 + g;
            #pragma unroll
            for (int n = 0; n < 6; n++) {
                int col = n0 + n * 8 + tig * 2;
                *(float2*)&smf[row * LDE + col]       = make_float2(acc[i][n][0], acc[i][n][1]);
                *(float2*)&smf[(row + 8) * LDE + col] = make_float2(acc[i][n][2], acc[i][n][3]);
            }
        }
    }
    __syncthreads();

    int s_idx = dir ? (Sq - 1 - t) : t;
    #pragma unroll 4
    for (int e = 0; e < 32; e++) {
        int idx = e * 256 + tid;
        int row = idx >> 6;        // 0..127
        int sub = idx & 63;
        int b = bm + row;
        int tok = (mode == 0) ? src[b * Sq + s_idx] : g_tok[b];
        const float* gi = tab + (size_t)tok * Ntot + bn;
        float gh_r = smf[row * LDE + sub];
        float gh_z = smf[row * LDE + 64 + sub];
        float gh_n = smf[row * LDE + 128 + sub];
        float rr = sigf(gi[sub]       + gh_r + bh[bn + sub]);
        float zz = sigf(gi[64 + sub]  + gh_z + bh[bn + 64 + sub]);
        float nn = tanhf(gi[128 + sub] + rr * (gh_n + bh[bn + 128 + sub]));
        int hcol = bx * 64 + sub;
        size_t ho_off = (size_t)b * Hloc + hcol;
        float hp = hprevf[ho_off];
        float ho = (1.f - zz) * nn + zz * hp;
        houtf[ho_off] = ho;
        __nv_bfloat16 hh = __float2bfloat16(ho);
        houthi[ho_off] = hh;
        houtlo[ho_off] = __float2bfloat16(ho - __bfloat162float(hh));
    }
}

// ---------------------------------------------------------------------------
// Concat encoder final states -> decoder h0 (ping 0)
// ---------------------------------------------------------------------------
__global__ void concat_kernel()
{
    int i = blockIdx.x * 256 + threadIdx.x;  // < 512*2048
    int b = i >> 11, j = i & 2047;
    float v = (j < Hq) ? g_h_e[0][0][b][j] : g_h_e[1][0][b][j - Hq];
    g_hdec_f[0][b][j] = v;
    __nv_bfloat16 h = __float2bfloat16(v);
    g_hhi_d[0][b][j] = h;
    g_hlo_d[0][b][j] = __float2bfloat16(v - __bfloat162float(h));
}

// ---------------------------------------------------------------------------
// Logits partials via bf16x3 mma: h[512,2048] @ W_fc[128,2048]^T, K-split x16
// grid (16 ksplit, 4 mtile), tile 128x128, K=128/split (2 chunks of 64)
// ---------------------------------------------------------------------------
#define LOG_SMEM (2 * 65536 + 1024)

__global__ __launch_bounds__(256, 1) void logits_mma_kernel(int t)
{
    extern __shared__ char smraw[];
    u32 raw = smem_u32(smraw);
    u32 base = (raw + 1023) & ~1023u;

    int tid = threadIdx.x, wid = tid >> 5, lane = tid & 31;
    int ks = blockIdx.x;
    int bm = blockIdx.y * 128;
    const int K = H2q;
    int kb0 = ks * 128;
    int pb = (t + 1) & 1;

    const __nv_bfloat16* pAh = &g_hhi_d[pb][0][0] + (size_t)bm * K;
    const __nv_bfloat16* pAl = &g_hlo_d[pb][0][0] + (size_t)bm * K;
    const __nv_bfloat16* pBh = &g_Wfc_hi[0][0];
    const __nv_bfloat16* pBl = &g_Wfc_lo[0][0];

    int m0 = (wid >> 2) * 64;
    int n0 = (wid & 3) * 32;

    float acc[4][4][4];
    #pragma unroll
    for (int i = 0; i < 4; i++)
        #pragma unroll
        for (int n = 0; n < 4; n++)
            #pragma unroll
            for (int q = 0; q < 4; q++) acc[i][n][q] = 0.f;

    #define LSTAGE(stg, kb) do {                                             \
        u32 sb_ = base + (stg) * 65536;                                      \
        _Pragma("unroll")                                                    \
        for (int p = 0; p < 16; p++) {                                       \
            int u_ = tid + 256 * p; int row_ = u_ >> 3, c_ = u_ & 7;         \
            int sec_ = row_ >> 7; int r_ = row_ & 127;                       \
            const __nv_bfloat16* g_ =                                        \
                (sec_ == 0 ? pAh : sec_ == 1 ? pAl : sec_ == 2 ? pBh : pBl)  \
                + (size_t)r_ * K + kb0 + (kb) + c_ * 8;                      \
            cp16(sb_ + sec_ * 16384u + swz(r_ * 128 + c_ * 16), g_);         \
        }                                                                    \
    } while (0)

    LSTAGE(0, 0);
    cp_commit();

    #pragma unroll
    for (int c = 0; c < 2; c++) {
        int s = c & 1;
        __syncthreads();
        if (c == 0) { LSTAGE(1, 64); cp_commit(); cp_wait1(); }
        else        { cp_wait0(); }
        __syncthreads();

        u32 buf = base + s * 65536;
        int arow = lane & 15;
        int acol = (lane >> 4) * 16;

        #pragma unroll
        for (int kss = 0; kss < 4; kss++) {
            int obyte = kss * 32 + acol;
            u32 af[2][4][4];
            u32 bf[2][2][4];
            #pragma unroll
            for (int i = 0; i < 4; i++) {
                u32 off = swz((m0 + i * 16 + arow) * 128 + obyte);
                ldsm4(buf + off,         af[0][i][0], af[0][i][1], af[0][i][2], af[0][i][3]);
                ldsm4(buf + 16384 + off, af[1][i][0], af[1][i][1], af[1][i][2], af[1][i][3]);
            }
            #pragma unroll
            for (int j = 0; j < 2; j++) {
                u32 off = swz((n0 + j * 16 + arow) * 128 + obyte);
                ldsm4(buf + 32768 + off, bf[0][j][0], bf[0][j][1], bf[0][j][2], bf[0][j][3]);
                ldsm4(buf + 49152 + off, bf[1][j][0], bf[1][j][1], bf[1][j][2], bf[1][j][3]);
            }
            #pragma unroll
            for (int i = 0; i < 4; i++) {
                #pragma unroll
                for (int j = 0; j < 2; j++) {
                    #pragma unroll
                    for (int q = 0; q < 2; q++) {
                        int n = j * 2 + q;
                        mma16816(acc[i][n], af[0][i], bf[0][j][q], bf[0][j][q + 2]);
                        mma16816(acc[i][n], af[0][i], bf[1][j][q], bf[1][j][q + 2]);
                        mma16816(acc[i][n], af[1][i], bf[0][j][q], bf[0][j][q + 2]);
                    }
                }
            }
        }
    }

    int g = lane >> 2, tig = lane & 3;
    #pragma unroll
    for (int i = 0; i < 4; i++) {
        int row0 = bm + m0 + i * 16 + g;
        #pragma unroll
        for (int n = 0; n < 4; n++) {
            int col = n0 + n * 8 + tig * 2;
            *(float2*)&g_lpart[ks][row0][col]     = make_float2(acc[i][n][0], acc[i][n][1]);
            *(float2*)&g_lpart[ks][row0 + 8][col] = make_float2(acc[i][n][2], acc[i][n][3]);
        }
    }
}

// ---------------------------------------------------------------------------
// Reduce partials + bias, write logits, argmax -> g_tok
// ---------------------------------------------------------------------------
__global__ __launch_bounds__(128) void reduce_argmax_kernel(
    const float* __restrict__ bfc, float* __restrict__ out, int t)
{
    int b = blockIdx.x;
    int v = threadIdx.x;
    float s = bfc[v];
    #pragma unroll
    for (int ks = 0; ks < 16; ks++) s += g_lpart[ks][b][v];
    out[((size_t)b * (Tq - 1) + t) * Vq + v] = s;

    __shared__ float sv[128];
    __shared__ int   si[128];
    sv[v] = s; si[v] = v;
    __syncthreads();
    #pragma unroll
    for (int off = 64; off > 0; off >>= 1) {
        if (v < off) {
            float o = sv[v + off]; int oi = si[v + off];
            if (o > sv[v] || (o == sv[v] && oi < si[v])) { sv[v] = o; si[v] = oi; }
        }
        __syncthreads();
    }
    if (v == 0) g_tok[b] = si[0];
}

// ---------------------------------------------------------------------------
extern "C" void kernel_launch(void* const* d_in, const int* in_sizes, int n_in,
                              void* d_out, int out_size)
{
    const int*   src     = (const int*)d_in[0];
    const int*   tgt     = (const int*)d_in[1];
    const float* enc_emb = (const float*)d_in[2];
    const float* dec_emb = (const float*)d_in[3];
    const float* W_ih_f  = (const float*)d_in[4];
    const float* W_hh_f  = (const float*)d_in[5];
    const float* b_ih_f  = (const float*)d_in[6];
    const float* b_hh_f  = (const float*)d_in[7];
    const float* W_ih_b  = (const float*)d_in[8];
    const float* W_hh_b  = (const float*)d_in[9];
    const float* b_ih_b  = (const float*)d_in[10];
    const float* b_hh_b  = (const float*)d_in[11];
    const float* W_ih_d  = (const float*)d_in[12];
    const float* W_hh_d  = (const float*)d_in[13];
    const float* b_ih_d  = (const float*)d_in[14];
    const float* b_hh_d  = (const float*)d_in[15];
    const float* W_fc    = (const float*)d_in[16];
    const float* b_fc    = (const float*)d_in[17];
    float* out = (float*)d_out;

    cudaFuncSetAttribute(gru_step_kernel,
                         cudaFuncAttributeMaxDynamicSharedMemorySize, GEMM_SMEM);
    cudaFuncSetAttribute(logits_mma_kernel,
                         cudaFuncAttributeMaxDynamicSharedMemorySize, LOG_SMEM);

    __nv_bfloat16 *whi_e0, *wlo_e0, *whi_d, *wlo_d, *wfc_hi, *wfc_lo;
    cudaGetSymbolAddress((void**)&whi_e0, g_Whi_e);
    cudaGetSymbolAddress((void**)&wlo_e0, g_Wlo_e);
    cudaGetSymbolAddress((void**)&whi_d,  g_Whi_d);
    cudaGetSymbolAddress((void**)&wlo_d,  g_Wlo_d);
    cudaGetSymbolAddress((void**)&wfc_hi, g_Wfc_hi);
    cudaGetSymbolAddress((void**)&wfc_lo, g_Wfc_lo);
    __nv_bfloat16* whi_e1 = whi_e0 + (size_t)G3H * Hq;
    __nv_bfloat16* wlo_e1 = wlo_e0 + (size_t)G3H * Hq;

    // Weight splits (recurrent: permuted; fc: natural)
    {
        int n1 = G3H * Hq;
        int n2 = G6H * H2q;
        int n3 = Vq * H2q;
        wsplit_perm_kernel<<<(n1 + 255) / 256, 256>>>(W_hh_f, whi_e0, wlo_e0, Hq, Hq, n1);
        wsplit_perm_kernel<<<(n1 + 255) / 256, 256>>>(W_hh_b, whi_e1, wlo_e1, Hq, Hq, n1);
        wsplit_perm_kernel<<<(n2 + 255) / 256, 256>>>(W_hh_d, whi_d, wlo_d, H2q, H2q, n2);
        wsplit_kernel<<<(n3 + 255) / 256, 256>>>(W_fc, wfc_hi, wfc_lo, n3);
    }
    bperm_kernel<<<24, 256>>>(b_hh_f, b_hh_b, b_hh_d);

    // Projection tables (permuted), init states/tokens
    table_kernel<<<dim3(96, 2, 3), 256>>>(enc_emb, dec_emb,
                                          W_ih_f, b_ih_f, W_ih_b, b_ih_b, W_ih_d, b_ih_d);
    init_kernel<<<4096, 256>>>(tgt);

    // Bidirectional encoder: fused GEMM+GRU, single wave (128 CTAs)
    for (int t = 0; t < Sq; t++)
        gru_step_kernel<<<dim3(16, 4, 2), 256, GEMM_SMEM>>>(0, t, src);

    // decoder h0 = concat(h_fwd, h_bwd)
    concat_kernel<<<4096, 256>>>();

    // Greedy decoder: fused GEMM+GRU (128 CTAs) + mma logits + argmax
    for (int t = 0; t < Tq - 1; t++) {
        gru_step_kernel<<<dim3(32, 4, 1), 256, GEMM_SMEM>>>(1, t, src);
        logits_mma_kernel<<<dim3(16, 4), 256, LOG_SMEM>>>(t);
        reduce_argmax_kernel<<<Bq, 128>>>(b_fc, out, t);
    }
}

// round 14
// speedup vs baseline: 2.4906x; 1.1551x over previous
#include <cuda_runtime.h>
#include <cuda_bf16.h>
#include <math.h>

// Problem dims
#define Bq   512
#define Sq   64
#define Tq   32
#define Eq   512
#define Hq   1024
#define H2q  2048
#define G3H  3072   // 3*H
#define G6H  6144   // 3*2H
#define Vq   128

typedef unsigned long long u64;
typedef unsigned int u32;

// ---------------------------------------------------------------------------
// Scratch (device statics; allocation-free)
// Weight/table/bias arrays live in gate-grouped PERMUTED layout:
//   original row (g*H + j)  ->  permuted row (j/64)*192 + g*64 + (j%64)
// ---------------------------------------------------------------------------
__device__ float g_encA[2][Vq][G3H];        // gi tables (permuted, incl b_ih)
__device__ float g_decA[Vq][G6H];           // decoder gi table (permuted)
__device__ float g_bhe[2][G3H];             // b_hh enc (permuted)
__device__ float g_bhd[G6H];                // b_hh dec (permuted)
__device__ float g_lpart[16][Bq][Vq];       // logits K-split partials
__device__ int   g_tok[Bq];                 // current decoder tokens

// hidden states (ping-pong)
__device__ float g_h_e[2][2][Bq][Hq];                 // [dir][pp][b][h]
__device__ float g_hdec_f[2][Bq][H2q];                // [pp][b][2h]
__device__ __nv_bfloat16 g_hhi_e[2][2][Bq][Hq], g_hlo_e[2][2][Bq][Hq];
__device__ __nv_bfloat16 g_hhi_d[2][Bq][H2q],   g_hlo_d[2][Bq][H2q];

// bf16 hi/lo split weights (recurrent: permuted; fc: natural)
__device__ __nv_bfloat16 g_Whi_e[2][G3H][Hq], g_Wlo_e[2][G3H][Hq];
__device__ __nv_bfloat16 g_Whi_d[G6H][H2q],   g_Wlo_d[G6H][H2q];
__device__ __nv_bfloat16 g_Wfc_hi[Vq][H2q],   g_Wfc_lo[Vq][H2q];

// ---------------------------------------------------------------------------
// Helpers
// ---------------------------------------------------------------------------
__device__ __forceinline__ float sigf(float x) { return 1.0f / (1.0f + expf(-x)); }

__device__ __forceinline__ u32 smem_u32(const void* p) {
    u32 a;
    asm("{ .reg .u64 t; cvta.to.shared.u64 t, %1; cvt.u32.u64 %0, t; }" : "=r"(a) : "l"(p));
    return a;
}
__device__ __forceinline__ u32 swz(u32 o) { return o ^ ((o >> 3) & 0x70); }

__device__ __forceinline__ void cp16(u32 saddr, const void* gaddr) {
    asm volatile("cp.async.cg.shared.global [%0], [%1], 16;" :: "r"(saddr), "l"(gaddr) : "memory");
}
__device__ __forceinline__ void cp_commit() {
    asm volatile("cp.async.commit_group;" ::: "memory");
}
__device__ __forceinline__ void cp_wait1() {
    asm volatile("cp.async.wait_group 1;" ::: "memory");
}
__device__ __forceinline__ void cp_wait0() {
    asm volatile("cp.async.wait_group 0;" ::: "memory");
}
__device__ __forceinline__ void ldsm4(u32 addr, u32& r0, u32& r1, u32& r2, u32& r3) {
    asm volatile("ldmatrix.sync.aligned.m8n8.x4.shared.b16 {%0,%1,%2,%3}, [%4];"
                 : "=r"(r0), "=r"(r1), "=r"(r2), "=r"(r3) : "r"(addr));
}
__device__ __forceinline__ void mma16816(float* c, const u32* a, u32 b0, u32 b1) {
    asm volatile(
        "mma.sync.aligned.m16n8k16.row.col.f32.bf16.bf16.f32 "
        "{%0,%1,%2,%3}, {%4,%5,%6,%7}, {%8,%9}, {%0,%1,%2,%3};"
        : "+f"(c[0]), "+f"(c[1]), "+f"(c[2]), "+f"(c[3])
        : "r"(a[0]), "r"(a[1]), "r"(a[2]), "r"(a[3]), "r"(b0), "r"(b1));
}

// ---------------------------------------------------------------------------
// Projection tables: C[M=128, N] = A[128,512] @ W[N,512]^T + bias[N]
// writes PERMUTED (gate-grouped) layout
// ---------------------------------------------------------------------------
__global__ __launch_bounds__(256) void table_kernel(
    const float* __restrict__ enc_emb, const float* __restrict__ dec_emb,
    const float* __restrict__ Wf, const float* __restrict__ bf,
    const float* __restrict__ Wb, const float* __restrict__ bb,
    const float* __restrict__ Wd, const float* __restrict__ bd)
{
    int z = blockIdx.z;
    const float* A; const float* W; const float* bias; float* out; int N; int H;
    if (z == 0)      { A = enc_emb; W = Wf; bias = bf; out = &g_encA[0][0][0]; N = G3H; H = Hq; }
    else if (z == 1) { A = enc_emb; W = Wb; bias = bb; out = &g_encA[1][0][0]; N = G3H; H = Hq; }
    else             { A = dec_emb; W = Wd; bias = bd; out = &g_decA[0][0];    N = G6H; H = H2q; }

    int bn = blockIdx.x * 64;
    if (bn >= N) return;
    int bm = blockIdx.y * 64;
    const int K = Eq;

    __shared__ float As[16][68];
    __shared__ float Bs[16][68];

    int tid = threadIdx.x;
    int tx = tid & 15, ty = tid >> 4;
    int lr = tid >> 2, lc = tid & 3;

    float acc[4][4];
    #pragma unroll
    for (int i = 0; i < 4; i++)
        #pragma unroll
        for (int j = 0; j < 4; j++) acc[i][j] = 0.f;

    for (int k0 = 0; k0 < K; k0 += 16) {
        float4 a4 = *(const float4*)&A[(bm + lr) * K + k0 + lc * 4];
        float4 w4 = *(const float4*)&W[(bn + lr) * K + k0 + lc * 4];
        As[lc*4+0][lr] = a4.x; As[lc*4+1][lr] = a4.y; As[lc*4+2][lr] = a4.z; As[lc*4+3][lr] = a4.w;
        Bs[lc*4+0][lr] = w4.x; Bs[lc*4+1][lr] = w4.y; Bs[lc*4+2][lr] = w4.z; Bs[lc*4+3][lr] = w4.w;
        __syncthreads();
        #pragma unroll
        for (int k = 0; k < 16; k++) {
            float4 av = *(const float4*)&As[k][ty * 4];
            float4 bv = *(const float4*)&Bs[k][tx * 4];
            float am[4] = {av.x, av.y, av.z, av.w};
            float bm4[4] = {bv.x, bv.y, bv.z, bv.w};
            #pragma unroll
            for (int i = 0; i < 4; i++)
                #pragma unroll
                for (int j = 0; j < 4; j++) acc[i][j] += am[i] * bm4[j];
        }
        __syncthreads();
    }

    #pragma unroll
    for (int i = 0; i < 4; i++) {
        int m = bm + ty * 4 + i;
        #pragma unroll
        for (int j = 0; j < 4; j++) {
            int n = bn + tx * 4 + j;
            int g = n / H, jj = n % H;
            int pn = (jj >> 6) * 192 + g * 64 + (jj & 63);
            out[m * N + pn] = acc[i][j] + bias[n];
        }
    }
}

// ---------------------------------------------------------------------------
// Weight splits
// ---------------------------------------------------------------------------
__global__ void wsplit_kernel(const float* __restrict__ w,
                              __nv_bfloat16* __restrict__ hi,
                              __nv_bfloat16* __restrict__ lo, int n)
{
    int i = blockIdx.x * 256 + threadIdx.x;
    if (i >= n) return;
    float x = w[i];
    __nv_bfloat16 h = __float2bfloat16(x);
    hi[i] = h;
    lo[i] = __float2bfloat16(x - __bfloat162float(h));
}

// permuted split for recurrent weights [3H, K]
__global__ void wsplit_perm_kernel(const float* __restrict__ w,
                                   __nv_bfloat16* __restrict__ hi,
                                   __nv_bfloat16* __restrict__ lo,
                                   int H, int K, int n)
{
    int i = blockIdx.x * 256 + threadIdx.x;
    if (i >= n) return;
    int row = i / K, col = i % K;
    int g = row / H, jj = row % H;
    int prow = (jj >> 6) * 192 + g * 64 + (jj & 63);
    float x = w[i];
    __nv_bfloat16 h = __float2bfloat16(x);
    size_t o = (size_t)prow * K + col;
    hi[o] = h;
    lo[o] = __float2bfloat16(x - __bfloat162float(h));
}

// permute b_hh vectors
__global__ void bperm_kernel(const float* __restrict__ bf,
                             const float* __restrict__ bb,
                             const float* __restrict__ bd)
{
    int i = blockIdx.x * 256 + threadIdx.x;
    if (i < 2 * G3H) {
        int d = i / G3H, n = i % G3H;
        int g = n / Hq, jj = n % Hq;
        g_bhe[d][(jj >> 6) * 192 + g * 64 + (jj & 63)] = d ? bb[n] : bf[n];
    }
    if (i < G6H) {
        int g = i / H2q, jj = i % H2q;
        g_bhd[(jj >> 6) * 192 + g * 64 + (jj & 63)] = bd[i];
    }
}

// ---------------------------------------------------------------------------
// Init: zero encoder ping-0 states, load initial tokens
// ---------------------------------------------------------------------------
__global__ void init_kernel(const int* __restrict__ tgt)
{
    int i = blockIdx.x * 256 + threadIdx.x;   // < 2*512*1024
    if (i < 2 * Bq * Hq) {
        int d = i / (Bq * Hq), off = i % (Bq * Hq);
        (&g_h_e[d][0][0][0])[off] = 0.f;
        (&g_hhi_e[d][0][0][0])[off] = __float2bfloat16(0.f);
        (&g_hlo_e[d][0][0][0])[off] = __float2bfloat16(0.f);
    }
    if (i < Bq) g_tok[i] = tgt[i * Tq + 0];
}

// ---------------------------------------------------------------------------
// Fused GRU step: gh = h @ Wperm^T (bf16x3 mma), then GRU update in epilogue.
// 512 threads / 16 warps, warp tile 32x48 (4x4 warp grid over 128x192 tile).
// mode 0: encoder (z=dir, K=1024, grid 16x4x2 = 128 CTAs)
// mode 1: decoder (K=2048, grid 32x4x1 = 128 CTAs)
// K-chunk 64 double-buffered cp.async; mma grouped by split-term for ILP.
// ---------------------------------------------------------------------------
#define STGB 81920
#define GEMM_SMEM (2 * STGB + 1024)
#define LDE 196

__global__ __launch_bounds__(512, 1) void gru_step_kernel(int mode, int t,
                                                          const int* __restrict__ src)
{
    extern __shared__ char smraw[];
    u32 raw = smem_u32(smraw);
    u32 base = (raw + 1023) & ~1023u;

    int tid = threadIdx.x, wid = tid >> 5, lane = tid & 31;
    int bx = blockIdx.x, bm = blockIdx.y * 128;

    int K, Ntot, dir = 0;
    const __nv_bfloat16 *pAh, *pAl, *pBh, *pBl;
    const float *tab, *bh, *hprevf;
    float* houtf; __nv_bfloat16 *houthi, *houtlo;
    if (mode == 0) {
        dir = blockIdx.z;
        K = Hq; Ntot = G3H;
        int pp = t & 1, pn = pp ^ 1;
        pAh = &g_hhi_e[dir][pp][0][0]; pAl = &g_hlo_e[dir][pp][0][0];
        pBh = &g_Whi_e[dir][0][0];     pBl = &g_Wlo_e[dir][0][0];
        tab = &g_encA[dir][0][0];      bh  = &g_bhe[dir][0];
        hprevf = &g_h_e[dir][pp][0][0];
        houtf  = &g_h_e[dir][pn][0][0];
        houthi = &g_hhi_e[dir][pn][0][0]; houtlo = &g_hlo_e[dir][pn][0][0];
    } else {
        K = H2q; Ntot = G6H;
        int pp = t & 1, pn = pp ^ 1;
        pAh = &g_hhi_d[pp][0][0]; pAl = &g_hlo_d[pp][0][0];
        pBh = &g_Whi_d[0][0];     pBl = &g_Wlo_d[0][0];
        tab = &g_decA[0][0];      bh  = &g_bhd[0];
        hprevf = &g_hdec_f[pp][0][0];
        houtf  = &g_hdec_f[pn][0][0];
        houthi = &g_hhi_d[pn][0][0]; houtlo = &g_hlo_d[pn][0][0];
    }
    const int Hloc = K;
    const int NC = K / 64;
    int bn = bx * 192;
    pAh += (size_t)bm * K; pAl += (size_t)bm * K;
    pBh += (size_t)bn * K; pBl += (size_t)bn * K;

    // warp tile: 4x4 grid of 32x48
    int m0 = (wid >> 2) * 32;
    int n0 = (wid & 3) * 48;

    float acc[2][6][4];   // [m-atom][n-atom][quad]
    #pragma unroll
    for (int i = 0; i < 2; i++)
        #pragma unroll
        for (int n = 0; n < 6; n++)
            #pragma unroll
            for (int q = 0; q < 4; q++) acc[i][n][q] = 0.f;

    // ---- staging (A: 256 rows x 128B, B: 384 rows x 128B) 512 threads ----
    #define STAGE(stg, kb) do {                                              \
        u32 sb_ = base + (stg) * STGB;                                       \
        _Pragma("unroll")                                                    \
        for (int p = 0; p < 4; p++) {                                        \
            int u_ = tid + 512 * p; int row_ = u_ >> 3, c_ = u_ & 7;         \
            int r_ = row_ & 127;                                             \
            const __nv_bfloat16* g_ = (row_ < 128 ? pAh : pAl)               \
                                      + (size_t)r_ * K + (kb) + c_ * 8;      \
            cp16(sb_ + (row_ < 128 ? 0u : 16384u) + swz(r_ * 128 + c_ * 16), g_); \
        }                                                                    \
        _Pragma("unroll")                                                    \
        for (int p = 0; p < 6; p++) {                                        \
            int u_ = tid + 512 * p; int row_ = u_ >> 3, c_ = u_ & 7;         \
            int r_ = (row_ < 192) ? row_ : row_ - 192;                       \
            const __nv_bfloat16* g_ = (row_ < 192 ? pBh : pBl)               \
                                      + (size_t)r_ * K + (kb) + c_ * 8;      \
            cp16(sb_ + (row_ < 192 ? 32768u : 57344u) + swz(r_ * 128 + c_ * 16), g_); \
        }                                                                    \
    } while (0)

    STAGE(0, 0);
    cp_commit();

    for (int c = 0; c < NC; c++) {
        int s = c & 1;
        __syncthreads();
        if (c + 1 < NC) {
            STAGE(s ^ 1, (size_t)(c + 1) * 64);
            cp_commit();
            cp_wait1();
        } else {
            cp_wait0();
        }
        __syncthreads();

        u32 buf = base + s * STGB;
        int arow = lane & 15;
        int acol = (lane >> 4) * 16;

        #pragma unroll
        for (int ks = 0; ks < 4; ks++) {
            int obyte = ks * 32 + acol;
            u32 af[2][2][4];   // [split][m-atom][4]
            u32 bf[2][3][4];   // [split][n16][4]
            #pragma unroll
            for (int i = 0; i < 2; i++) {
                u32 off = swz((m0 + i * 16 + arow) * 128 + obyte);
                ldsm4(buf + off,          af[0][i][0], af[0][i][1], af[0][i][2], af[0][i][3]);
                ldsm4(buf + 16384 + off,  af[1][i][0], af[1][i][1], af[1][i][2], af[1][i][3]);
            }
            #pragma unroll
            for (int j = 0; j < 3; j++) {
                u32 off = swz((n0 + j * 16 + arow) * 128 + obyte);
                ldsm4(buf + 32768 + off,  bf[0][j][0], bf[0][j][1], bf[0][j][2], bf[0][j][3]);
                ldsm4(buf + 57344 + off,  bf[1][j][0], bf[1][j][1], bf[1][j][2], bf[1][j][3]);
            }
            // grouped by split-term: 12 independent mmas per group
            #pragma unroll
            for (int i = 0; i < 2; i++)
                #pragma unroll
                for (int j = 0; j < 3; j++)
                    #pragma unroll
                    for (int q = 0; q < 2; q++)
                        mma16816(acc[i][j * 2 + q], af[0][i], bf[0][j][q], bf[0][j][q + 2]);
            #pragma unroll
            for (int i = 0; i < 2; i++)
                #pragma unroll
                for (int j = 0; j < 3; j++)
                    #pragma unroll
                    for (int q = 0; q < 2; q++)
                        mma16816(acc[i][j * 2 + q], af[0][i], bf[1][j][q], bf[1][j][q + 2]);
            #pragma unroll
            for (int i = 0; i < 2; i++)
                #pragma unroll
                for (int j = 0; j < 3; j++)
                    #pragma unroll
                    for (int q = 0; q < 2; q++)
                        mma16816(acc[i][j * 2 + q], af[1][i], bf[0][j][q], bf[0][j][q + 2]);
        }
    }

    // ---- epilogue: acc -> smem, recombine gate triples, GRU update ----
    __syncthreads();
    float* smf = (float*)smraw;
    {
        int g = lane >> 2, tig = lane & 3;
        #pragma unroll
        for (int i = 0; i < 2; i++) {
            int row = m0 + i * 16 + g;
            #pragma unroll
            for (int n = 0; n < 6; n++) {
                int col = n0 + n * 8 + tig * 2;
                *(float2*)&smf[row * LDE + col]       = make_float2(acc[i][n][0], acc[i][n][1]);
                *(float2*)&smf[(row + 8) * LDE + col] = make_float2(acc[i][n][2], acc[i][n][3]);
            }
        }
    }
    __syncthreads();

    int s_idx = dir ? (Sq - 1 - t) : t;
    #pragma unroll 4
    for (int e = 0; e < 16; e++) {
        int idx = e * 512 + tid;
        int row = idx >> 6;        // 0..127
        int sub = idx & 63;
        int b = bm + row;
        int tok = (mode == 0) ? src[b * Sq + s_idx] : g_tok[b];
        const float* gi = tab + (size_t)tok * Ntot + bn;
        float gh_r = smf[row * LDE + sub];
        float gh_z = smf[row * LDE + 64 + sub];
        float gh_n = smf[row * LDE + 128 + sub];
        float rr = sigf(gi[sub]       + gh_r + bh[bn + sub]);
        float zz = sigf(gi[64 + sub]  + gh_z + bh[bn + 64 + sub]);
        float nn = tanhf(gi[128 + sub] + rr * (gh_n + bh[bn + 128 + sub]));
        int hcol = bx * 64 + sub;
        size_t ho_off = (size_t)b * Hloc + hcol;
        float hp = hprevf[ho_off];
        float ho = (1.f - zz) * nn + zz * hp;
        houtf[ho_off] = ho;
        __nv_bfloat16 hh = __float2bfloat16(ho);
        houthi[ho_off] = hh;
        houtlo[ho_off] = __float2bfloat16(ho - __bfloat162float(hh));
    }
}

// ---------------------------------------------------------------------------
// Concat encoder final states -> decoder h0 (ping 0)
// ---------------------------------------------------------------------------
__global__ void concat_kernel()
{
    int i = blockIdx.x * 256 + threadIdx.x;  // < 512*2048
    int b = i >> 11, j = i & 2047;
    float v = (j < Hq) ? g_h_e[0][0][b][j] : g_h_e[1][0][b][j - Hq];
    g_hdec_f[0][b][j] = v;
    __nv_bfloat16 h = __float2bfloat16(v);
    g_hhi_d[0][b][j] = h;
    g_hlo_d[0][b][j] = __float2bfloat16(v - __bfloat162float(h));
}

// ---------------------------------------------------------------------------
// Logits partials via bf16x3 mma: h[512,2048] @ W_fc[128,2048]^T, K-split x16
// grid (16 ksplit, 4 mtile), tile 128x128, K=128/split (2 chunks of 64)
// ---------------------------------------------------------------------------
#define LOG_SMEM (2 * 65536 + 1024)

__global__ __launch_bounds__(256, 1) void logits_mma_kernel(int t)
{
    extern __shared__ char smraw[];
    u32 raw = smem_u32(smraw);
    u32 base = (raw + 1023) & ~1023u;

    int tid = threadIdx.x, wid = tid >> 5, lane = tid & 31;
    int ks = blockIdx.x;
    int bm = blockIdx.y * 128;
    const int K = H2q;
    int kb0 = ks * 128;
    int pb = (t + 1) & 1;

    const __nv_bfloat16* pAh = &g_hhi_d[pb][0][0] + (size_t)bm * K;
    const __nv_bfloat16* pAl = &g_hlo_d[pb][0][0] + (size_t)bm * K;
    const __nv_bfloat16* pBh = &g_Wfc_hi[0][0];
    const __nv_bfloat16* pBl = &g_Wfc_lo[0][0];

    int m0 = (wid >> 2) * 64;
    int n0 = (wid & 3) * 32;

    float acc[4][4][4];
    #pragma unroll
    for (int i = 0; i < 4; i++)
        #pragma unroll
        for (int n = 0; n < 4; n++)
            #pragma unroll
            for (int q = 0; q < 4; q++) acc[i][n][q] = 0.f;

    #define LSTAGE(stg, kb) do {                                             \
        u32 sb_ = base + (stg) * 65536;                                      \
        _Pragma("unroll")                                                    \
        for (int p = 0; p < 16; p++) {                                       \
            int u_ = tid + 256 * p; int row_ = u_ >> 3, c_ = u_ & 7;         \
            int sec_ = row_ >> 7; int r_ = row_ & 127;                       \
            const __nv_bfloat16* g_ =                                        \
                (sec_ == 0 ? pAh : sec_ == 1 ? pAl : sec_ == 2 ? pBh : pBl)  \
                + (size_t)r_ * K + kb0 + (kb) + c_ * 8;                      \
            cp16(sb_ + sec_ * 16384u + swz(r_ * 128 + c_ * 16), g_);         \
        }                                                                    \
    } while (0)

    LSTAGE(0, 0);
    cp_commit();

    #pragma unroll
    for (int c = 0; c < 2; c++) {
        int s = c & 1;
        __syncthreads();
        if (c == 0) { LSTAGE(1, 64); cp_commit(); cp_wait1(); }
        else        { cp_wait0(); }
        __syncthreads();

        u32 buf = base + s * 65536;
        int arow = lane & 15;
        int acol = (lane >> 4) * 16;

        #pragma unroll
        for (int kss = 0; kss < 4; kss++) {
            int obyte = kss * 32 + acol;
            u32 af[2][4][4];
            u32 bf[2][2][4];
            #pragma unroll
            for (int i = 0; i < 4; i++) {
                u32 off = swz((m0 + i * 16 + arow) * 128 + obyte);
                ldsm4(buf + off,         af[0][i][0], af[0][i][1], af[0][i][2], af[0][i][3]);
                ldsm4(buf + 16384 + off, af[1][i][0], af[1][i][1], af[1][i][2], af[1][i][3]);
            }
            #pragma unroll
            for (int j = 0; j < 2; j++) {
                u32 off = swz((n0 + j * 16 + arow) * 128 + obyte);
                ldsm4(buf + 32768 + off, bf[0][j][0], bf[0][j][1], bf[0][j][2], bf[0][j][3]);
                ldsm4(buf + 49152 + off, bf[1][j][0], bf[1][j][1], bf[1][j][2], bf[1][j][3]);
            }
            #pragma unroll
            for (int i = 0; i < 4; i++)
                #pragma unroll
                for (int j = 0; j < 2; j++)
                    #pragma unroll
                    for (int q = 0; q < 2; q++)
                        mma16816(acc[i][j * 2 + q], af[0][i], bf[0][j][q], bf[0][j][q + 2]);
            #pragma unroll
            for (int i = 0; i < 4; i++)
                #pragma unroll
                for (int j = 0; j < 2; j++)
                    #pragma unroll
                    for (int q = 0; q < 2; q++)
                        mma16816(acc[i][j * 2 + q], af[0][i], bf[1][j][q], bf[1][j][q + 2]);
            #pragma unroll
            for (int i = 0; i < 4; i++)
                #pragma unroll
                for (int j = 0; j < 2; j++)
                    #pragma unroll
                    for (int q = 0; q < 2; q++)
                        mma16816(acc[i][j * 2 + q], af[1][i], bf[0][j][q], bf[0][j][q + 2]);
        }
    }

    int g = lane >> 2, tig = lane & 3;
    #pragma unroll
    for (int i = 0; i < 4; i++) {
        int row0 = bm + m0 + i * 16 + g;
        #pragma unroll
        for (int n = 0; n < 4; n++) {
            int col = n0 + n * 8 + tig * 2;
            *(float2*)&g_lpart[ks][row0][col]     = make_float2(acc[i][n][0], acc[i][n][1]);
            *(float2*)&g_lpart[ks][row0 + 8][col] = make_float2(acc[i][n][2], acc[i][n][3]);
        }
    }
}

// ---------------------------------------------------------------------------
// Reduce partials + bias, write logits, argmax -> g_tok
// ---------------------------------------------------------------------------
__global__ __launch_bounds__(128) void reduce_argmax_kernel(
    const float* __restrict__ bfc, float* __restrict__ out, int t)
{
    int b = blockIdx.x;
    int v = threadIdx.x;
    float s = bfc[v];
    #pragma unroll
    for (int ks = 0; ks < 16; ks++) s += g_lpart[ks][b][v];
    out[((size_t)b * (Tq - 1) + t) * Vq + v] = s;

    __shared__ float sv[128];
    __shared__ int   si[128];
    sv[v] = s; si[v] = v;
    __syncthreads();
    #pragma unroll
    for (int off = 64; off > 0; off >>= 1) {
        if (v < off) {
            float o = sv[v + off]; int oi = si[v + off];
            if (o > sv[v] || (o == sv[v] && oi < si[v])) { sv[v] = o; si[v] = oi; }
        }
        __syncthreads();
    }
    if (v == 0) g_tok[b] = si[0];
}

// ---------------------------------------------------------------------------
extern "C" void kernel_launch(void* const* d_in, const int* in_sizes, int n_in,
                              void* d_out, int out_size)
{
    const int*   src     = (const int*)d_in[0];
    const int*   tgt     = (const int*)d_in[1];
    const float* enc_emb = (const float*)d_in[2];
    const float* dec_emb = (const float*)d_in[3];
    const float* W_ih_f  = (const float*)d_in[4];
    const float* W_hh_f  = (const float*)d_in[5];
    const float* b_ih_f  = (const float*)d_in[6];
    const float* b_hh_f  = (const float*)d_in[7];
    const float* W_ih_b  = (const float*)d_in[8];
    const float* W_hh_b  = (const float*)d_in[9];
    const float* b_ih_b  = (const float*)d_in[10];
    const float* b_hh_b  = (const float*)d_in[11];
    const float* W_ih_d  = (const float*)d_in[12];
    const float* W_hh_d  = (const float*)d_in[13];
    const float* b_ih_d  = (const float*)d_in[14];
    const float* b_hh_d  = (const float*)d_in[15];
    const float* W_fc    = (const float*)d_in[16];
    const float* b_fc    = (const float*)d_in[17];
    float* out = (float*)d_out;

    cudaFuncSetAttribute(gru_step_kernel,
                         cudaFuncAttributeMaxDynamicSharedMemorySize, GEMM_SMEM);
    cudaFuncSetAttribute(logits_mma_kernel,
                         cudaFuncAttributeMaxDynamicSharedMemorySize, LOG_SMEM);

    __nv_bfloat16 *whi_e0, *wlo_e0, *whi_d, *wlo_d, *wfc_hi, *wfc_lo;
    cudaGetSymbolAddress((void**)&whi_e0, g_Whi_e);
    cudaGetSymbolAddress((void**)&wlo_e0, g_Wlo_e);
    cudaGetSymbolAddress((void**)&whi_d,  g_Whi_d);
    cudaGetSymbolAddress((void**)&wlo_d,  g_Wlo_d);
    cudaGetSymbolAddress((void**)&wfc_hi, g_Wfc_hi);
    cudaGetSymbolAddress((void**)&wfc_lo, g_Wfc_lo);
    __nv_bfloat16* whi_e1 = whi_e0 + (size_t)G3H * Hq;
    __nv_bfloat16* wlo_e1 = wlo_e0 + (size_t)G3H * Hq;

    // Weight splits (recurrent: permuted; fc: natural)
    {
        int n1 = G3H * Hq;
        int n2 = G6H * H2q;
        int n3 = Vq * H2q;
        wsplit_perm_kernel<<<(n1 + 255) / 256, 256>>>(W_hh_f, whi_e0, wlo_e0, Hq, Hq, n1);
        wsplit_perm_kernel<<<(n1 + 255) / 256, 256>>>(W_hh_b, whi_e1, wlo_e1, Hq, Hq, n1);
        wsplit_perm_kernel<<<(n2 + 255) / 256, 256>>>(W_hh_d, whi_d, wlo_d, H2q, H2q, n2);
        wsplit_kernel<<<(n3 + 255) / 256, 256>>>(W_fc, wfc_hi, wfc_lo, n3);
    }
    bperm_kernel<<<24, 256>>>(b_hh_f, b_hh_b, b_hh_d);

    // Projection tables (permuted), init states/tokens
    table_kernel<<<dim3(96, 2, 3), 256>>>(enc_emb, dec_emb,
                                          W_ih_f, b_ih_f, W_ih_b, b_ih_b, W_ih_d, b_ih_d);
    init_kernel<<<4096, 256>>>(tgt);

    // Bidirectional encoder: fused GEMM+GRU, single wave (128 CTAs)
    for (int t = 0; t < Sq; t++)
        gru_step_kernel<<<dim3(16, 4, 2), 512, GEMM_SMEM>>>(0, t, src);

    // decoder h0 = concat(h_fwd, h_bwd)
    concat_kernel<<<4096, 256>>>();

    // Greedy decoder: fused GEMM+GRU (128 CTAs) + mma logits + argmax
    for (int t = 0; t < Tq - 1; t++) {
        gru_step_kernel<<<dim3(32, 4, 1), 512, GEMM_SMEM>>>(1, t, src);
        logits_mma_kernel<<<dim3(16, 4), 256, LOG_SMEM>>>(t);
        reduce_argmax_kernel<<<Bq, 128>>>(b_fc, out, t);
    }
}

// round 15
// speedup vs baseline: 2.6206x; 1.0522x over previous
#include <cuda_runtime.h>
#include <cuda_bf16.h>
#include <math.h>

// Problem dims
#define Bq   512
#define Sq   64
#define Tq   32
#define Eq   512
#define Hq   1024
#define H2q  2048
#define G3H  3072   // 3*H
#define G6H  6144   // 3*2H
#define Vq   128

typedef unsigned long long u64;
typedef unsigned int u32;

// ---------------------------------------------------------------------------
// Scratch (device statics; allocation-free)
// Weight/table/bias arrays live in gate-grouped PERMUTED layout:
//   original row (g*H + j)  ->  permuted row (j/64)*192 + g*64 + (j%64)
// ---------------------------------------------------------------------------
__device__ float g_encA[2][Vq][G3H];        // gi tables (permuted, incl b_ih)
__device__ float g_decA[Vq][G6H];           // decoder gi table (permuted)
__device__ float g_bhe[2][G3H];             // b_hh enc (permuted)
__device__ float g_bhd[G6H];                // b_hh dec (permuted)
__device__ float g_lpart[16][Bq][Vq];       // logits K-split partials
__device__ int   g_tok[Bq];                 // current decoder tokens

// hidden states (ping-pong)
__device__ float g_h_e[2][2][Bq][Hq];                 // [dir][pp][b][h]
__device__ float g_hdec_f[2][Bq][H2q];                // [pp][b][2h]
__device__ __nv_bfloat16 g_hhi_e[2][2][Bq][Hq], g_hlo_e[2][2][Bq][Hq];
__device__ __nv_bfloat16 g_hhi_d[2][Bq][H2q],   g_hlo_d[2][Bq][H2q];

// bf16 hi/lo split weights (recurrent: permuted; fc: natural)
__device__ __nv_bfloat16 g_Whi_e[2][G3H][Hq], g_Wlo_e[2][G3H][Hq];
__device__ __nv_bfloat16 g_Whi_d[G6H][H2q],   g_Wlo_d[G6H][H2q];
__device__ __nv_bfloat16 g_Wfc_hi[Vq][H2q],   g_Wfc_lo[Vq][H2q];

// ---------------------------------------------------------------------------
// Helpers
// ---------------------------------------------------------------------------
__device__ __forceinline__ float sigf(float x) { return 1.0f / (1.0f + __expf(-x)); }

__device__ __forceinline__ u32 smem_u32(const void* p) {
    u32 a;
    asm("{ .reg .u64 t; cvta.to.shared.u64 t, %1; cvt.u32.u64 %0, t; }" : "=r"(a) : "l"(p));
    return a;
}
__device__ __forceinline__ u32 swz(u32 o) { return o ^ ((o >> 3) & 0x70); }

__device__ __forceinline__ void cp16(u32 saddr, const void* gaddr) {
    asm volatile("cp.async.cg.shared.global [%0], [%1], 16;" :: "r"(saddr), "l"(gaddr) : "memory");
}
__device__ __forceinline__ void cp_commit() {
    asm volatile("cp.async.commit_group;" ::: "memory");
}
__device__ __forceinline__ void cp_wait1() {
    asm volatile("cp.async.wait_group 1;" ::: "memory");
}
__device__ __forceinline__ void cp_wait0() {
    asm volatile("cp.async.wait_group 0;" ::: "memory");
}
__device__ __forceinline__ void ldsm4(u32 addr, u32& r0, u32& r1, u32& r2, u32& r3) {
    asm volatile("ldmatrix.sync.aligned.m8n8.x4.shared.b16 {%0,%1,%2,%3}, [%4];"
                 : "=r"(r0), "=r"(r1), "=r"(r2), "=r"(r3) : "r"(addr));
}
__device__ __forceinline__ void mma16816(float* c, const u32* a, u32 b0, u32 b1) {
    asm volatile(
        "mma.sync.aligned.m16n8k16.row.col.f32.bf16.bf16.f32 "
        "{%0,%1,%2,%3}, {%4,%5,%6,%7}, {%8,%9}, {%0,%1,%2,%3};"
        : "+f"(c[0]), "+f"(c[1]), "+f"(c[2]), "+f"(c[3])
        : "r"(a[0]), "r"(a[1]), "r"(a[2]), "r"(a[3]), "r"(b0), "r"(b1));
}

// ---------------------------------------------------------------------------
// Unified prep kernel (ONE launch): weight hi/lo splits + bias permute.
// grid (49152, 5): task = blockIdx.y
//  0: W_hh_f -> g_Whi_e[0]/g_Wlo_e[0] (permuted)    n = G3H*Hq
//  1: W_hh_b -> g_Whi_e[1]/g_Wlo_e[1] (permuted)    n = G3H*Hq
//  2: W_hh_d -> g_Whi_d/g_Wlo_d       (permuted)    n = G6H*H2q
//  3: W_fc   -> g_Wfc_hi/g_Wfc_lo     (natural)     n = Vq*H2q
//  4: b_hh_{f,b,d} -> g_bhe/g_bhd     (permuted)
// ---------------------------------------------------------------------------
__global__ __launch_bounds__(256) void prep_kernel(
    const float* __restrict__ Wf, const float* __restrict__ Wb,
    const float* __restrict__ Wd, const float* __restrict__ Wfc,
    const float* __restrict__ bf, const float* __restrict__ bb,
    const float* __restrict__ bd)
{
    int task = blockIdx.y;
    int i = blockIdx.x * 256 + threadIdx.x;

    if (task <= 1) {
        if (i >= G3H * Hq) return;
        const float* w = task ? Wb : Wf;
        int row = i / Hq, col = i % Hq;
        int g = row / Hq, jj = row % Hq;
        g = row >> 10;                 // row / 1024
        jj = row & 1023;
        int prow = (jj >> 6) * 192 + g * 64 + (jj & 63);
        float x = w[i];
        __nv_bfloat16 h = __float2bfloat16(x);
        size_t o = (size_t)prow * Hq + col;
        g_Whi_e[task][0][o] = h;
        g_Wlo_e[task][0][o] = __float2bfloat16(x - __bfloat162float(h));
    } else if (task == 2) {
        if (i >= G6H * H2q) return;
        int row = i >> 11, col = i & 2047;
        int g = row >> 11, jj = row & 2047;
        int prow = (jj >> 6) * 192 + g * 64 + (jj & 63);
        float x = Wd[i];
        __nv_bfloat16 h = __float2bfloat16(x);
        size_t o = (size_t)prow * H2q + col;
        g_Whi_d[0][o] = h;
        g_Wlo_d[0][o] = __float2bfloat16(x - __bfloat162float(h));
    } else if (task == 3) {
        if (i >= Vq * H2q) return;
        float x = Wfc[i];
        __nv_bfloat16 h = __float2bfloat16(x);
        g_Wfc_hi[0][i] = h;
        g_Wfc_lo[0][i] = __float2bfloat16(x - __bfloat162float(h));
    } else {
        if (i < 2 * G3H) {
            int d = i / G3H, n = i % G3H;
            int g = n >> 10, jj = n & 1023;
            g_bhe[d][(jj >> 6) * 192 + g * 64 + (jj & 63)] = d ? bb[n] : bf[n];
        }
        if (i < G6H) {
            int g = i >> 11, jj = i & 2047;
            g_bhd[(jj >> 6) * 192 + g * 64 + (jj & 63)] = bd[i];
        }
    }
}

// ---------------------------------------------------------------------------
// Projection tables: C[M=128, N] = A[128,512] @ W[N,512]^T + bias[N]
// writes PERMUTED (gate-grouped) layout
// ---------------------------------------------------------------------------
__global__ __launch_bounds__(256) void table_kernel(
    const float* __restrict__ enc_emb, const float* __restrict__ dec_emb,
    const float* __restrict__ Wf, const float* __restrict__ bf,
    const float* __restrict__ Wb, const float* __restrict__ bb,
    const float* __restrict__ Wd, const float* __restrict__ bd)
{
    int z = blockIdx.z;
    const float* A; const float* W; const float* bias; float* out; int N; int H;
    if (z == 0)      { A = enc_emb; W = Wf; bias = bf; out = &g_encA[0][0][0]; N = G3H; H = Hq; }
    else if (z == 1) { A = enc_emb; W = Wb; bias = bb; out = &g_encA[1][0][0]; N = G3H; H = Hq; }
    else             { A = dec_emb; W = Wd; bias = bd; out = &g_decA[0][0];    N = G6H; H = H2q; }

    int bn = blockIdx.x * 64;
    if (bn >= N) return;
    int bm = blockIdx.y * 64;
    const int K = Eq;

    __shared__ float As[16][68];
    __shared__ float Bs[16][68];

    int tid = threadIdx.x;
    int tx = tid & 15, ty = tid >> 4;
    int lr = tid >> 2, lc = tid & 3;

    float acc[4][4];
    #pragma unroll
    for (int i = 0; i < 4; i++)
        #pragma unroll
        for (int j = 0; j < 4; j++) acc[i][j] = 0.f;

    for (int k0 = 0; k0 < K; k0 += 16) {
        float4 a4 = *(const float4*)&A[(bm + lr) * K + k0 + lc * 4];
        float4 w4 = *(const float4*)&W[(bn + lr) * K + k0 + lc * 4];
        As[lc*4+0][lr] = a4.x; As[lc*4+1][lr] = a4.y; As[lc*4+2][lr] = a4.z; As[lc*4+3][lr] = a4.w;
        Bs[lc*4+0][lr] = w4.x; Bs[lc*4+1][lr] = w4.y; Bs[lc*4+2][lr] = w4.z; Bs[lc*4+3][lr] = w4.w;
        __syncthreads();
        #pragma unroll
        for (int k = 0; k < 16; k++) {
            float4 av = *(const float4*)&As[k][ty * 4];
            float4 bv = *(const float4*)&Bs[k][tx * 4];
            float am[4] = {av.x, av.y, av.z, av.w};
            float bm4[4] = {bv.x, bv.y, bv.z, bv.w};
            #pragma unroll
            for (int i = 0; i < 4; i++)
                #pragma unroll
                for (int j = 0; j < 4; j++) acc[i][j] += am[i] * bm4[j];
        }
        __syncthreads();
    }

    #pragma unroll
    for (int i = 0; i < 4; i++) {
        int m = bm + ty * 4 + i;
        #pragma unroll
        for (int j = 0; j < 4; j++) {
            int n = bn + tx * 4 + j;
            int g = n / H, jj = n % H;
            int pn = (jj >> 6) * 192 + g * 64 + (jj & 63);
            out[m * N + pn] = acc[i][j] + bias[n];
        }
    }
}

// ---------------------------------------------------------------------------
// Init: zero encoder ping-0 states, load initial tokens
// ---------------------------------------------------------------------------
__global__ void init_kernel(const int* __restrict__ tgt)
{
    int i = blockIdx.x * 256 + threadIdx.x;   // < 2*512*1024
    if (i < 2 * Bq * Hq) {
        int d = i / (Bq * Hq), off = i % (Bq * Hq);
        (&g_h_e[d][0][0][0])[off] = 0.f;
        (&g_hhi_e[d][0][0][0])[off] = __float2bfloat16(0.f);
        (&g_hlo_e[d][0][0][0])[off] = __float2bfloat16(0.f);
    }
    if (i < Bq) g_tok[i] = tgt[i * Tq + 0];
}

// ---------------------------------------------------------------------------
// Fused GRU step: gh = h @ Wperm^T (bf16x3 mma), then GRU update in epilogue.
// 512 threads / 16 warps, warp tile 32x48 (4x4 warp grid over 128x192 tile).
// mode 0: encoder (z=dir, K=1024, grid 16x4x2 = 128 CTAs)
// mode 1: decoder (K=2048, grid 32x4x1 = 128 CTAs)
// K-chunk 64 double-buffered cp.async; mma grouped by split-term for ILP.
// ---------------------------------------------------------------------------
#define STGB 81920
#define GEMM_SMEM (2 * STGB + 1024)
#define LDE 196

__global__ __launch_bounds__(512, 1) void gru_step_kernel(int mode, int t,
                                                          const int* __restrict__ src)
{
    extern __shared__ char smraw[];
    u32 raw = smem_u32(smraw);
    u32 base = (raw + 1023) & ~1023u;

    int tid = threadIdx.x, wid = tid >> 5, lane = tid & 31;
    int bx = blockIdx.x, bm = blockIdx.y * 128;

    int K, Ntot, dir = 0;
    const __nv_bfloat16 *pAh, *pAl, *pBh, *pBl;
    const float *tab, *bh, *hprevf;
    float* houtf; __nv_bfloat16 *houthi, *houtlo;
    if (mode == 0) {
        dir = blockIdx.z;
        K = Hq; Ntot = G3H;
        int pp = t & 1, pn = pp ^ 1;
        pAh = &g_hhi_e[dir][pp][0][0]; pAl = &g_hlo_e[dir][pp][0][0];
        pBh = &g_Whi_e[dir][0][0];     pBl = &g_Wlo_e[dir][0][0];
        tab = &g_encA[dir][0][0];      bh  = &g_bhe[dir][0];
        hprevf = &g_h_e[dir][pp][0][0];
        houtf  = &g_h_e[dir][pn][0][0];
        houthi = &g_hhi_e[dir][pn][0][0]; houtlo = &g_hlo_e[dir][pn][0][0];
    } else {
        K = H2q; Ntot = G6H;
        int pp = t & 1, pn = pp ^ 1;
        pAh = &g_hhi_d[pp][0][0]; pAl = &g_hlo_d[pp][0][0];
        pBh = &g_Whi_d[0][0];     pBl = &g_Wlo_d[0][0];
        tab = &g_decA[0][0];      bh  = &g_bhd[0];
        hprevf = &g_hdec_f[pp][0][0];
        houtf  = &g_hdec_f[pn][0][0];
        houthi = &g_hhi_d[pn][0][0]; houtlo = &g_hlo_d[pn][0][0];
    }
    const int Hloc = K;
    const int NC = K / 64;
    int bn = bx * 192;
    pAh += (size_t)bm * K; pAl += (size_t)bm * K;
    pBh += (size_t)bn * K; pBl += (size_t)bn * K;

    // warp tile: 4x4 grid of 32x48
    int m0 = (wid >> 2) * 32;
    int n0 = (wid & 3) * 48;

    float acc[2][6][4];   // [m-atom][n-atom][quad]
    #pragma unroll
    for (int i = 0; i < 2; i++)
        #pragma unroll
        for (int n = 0; n < 6; n++)
            #pragma unroll
            for (int q = 0; q < 4; q++) acc[i][n][q] = 0.f;

    // ---- staging (A: 256 rows x 128B, B: 384 rows x 128B) 512 threads ----
    #define STAGE(stg, kb) do {                                              \
        u32 sb_ = base + (stg) * STGB;                                       \
        _Pragma("unroll")                                                    \
        for (int p = 0; p < 4; p++) {                                        \
            int u_ = tid + 512 * p; int row_ = u_ >> 3, c_ = u_ & 7;         \
            int r_ = row_ & 127;                                             \
            const __nv_bfloat16* g_ = (row_ < 128 ? pAh : pAl)               \
                                      + (size_t)r_ * K + (kb) + c_ * 8;      \
            cp16(sb_ + (row_ < 128 ? 0u : 16384u) + swz(r_ * 128 + c_ * 16), g_); \
        }                                                                    \
        _Pragma("unroll")                                                    \
        for (int p = 0; p < 6; p++) {                                        \
            int u_ = tid + 512 * p; int row_ = u_ >> 3, c_ = u_ & 7;         \
            int r_ = (row_ < 192) ? row_ : row_ - 192;                       \
            const __nv_bfloat16* g_ = (row_ < 192 ? pBh : pBl)               \
                                      + (size_t)r_ * K + (kb) + c_ * 8;      \
            cp16(sb_ + (row_ < 192 ? 32768u : 57344u) + swz(r_ * 128 + c_ * 16), g_); \
        }                                                                    \
    } while (0)

    STAGE(0, 0);
    cp_commit();

    for (int c = 0; c < NC; c++) {
        int s = c & 1;
        __syncthreads();
        if (c + 1 < NC) {
            STAGE(s ^ 1, (size_t)(c + 1) * 64);
            cp_commit();
            cp_wait1();
        } else {
            cp_wait0();
        }
        __syncthreads();

        u32 buf = base + s * STGB;
        int arow = lane & 15;
        int acol = (lane >> 4) * 16;

        #pragma unroll
        for (int ks = 0; ks < 4; ks++) {
            int obyte = ks * 32 + acol;
            u32 af[2][2][4];   // [split][m-atom][4]
            u32 bf[2][3][4];   // [split][n16][4]
            #pragma unroll
            for (int i = 0; i < 2; i++) {
                u32 off = swz((m0 + i * 16 + arow) * 128 + obyte);
                ldsm4(buf + off,          af[0][i][0], af[0][i][1], af[0][i][2], af[0][i][3]);
                ldsm4(buf + 16384 + off,  af[1][i][0], af[1][i][1], af[1][i][2], af[1][i][3]);
            }
            #pragma unroll
            for (int j = 0; j < 3; j++) {
                u32 off = swz((n0 + j * 16 + arow) * 128 + obyte);
                ldsm4(buf + 32768 + off,  bf[0][j][0], bf[0][j][1], bf[0][j][2], bf[0][j][3]);
                ldsm4(buf + 57344 + off,  bf[1][j][0], bf[1][j][1], bf[1][j][2], bf[1][j][3]);
            }
            // grouped by split-term: 12 independent mmas per group
            #pragma unroll
            for (int i = 0; i < 2; i++)
                #pragma unroll
                for (int j = 0; j < 3; j++)
                    #pragma unroll
                    for (int q = 0; q < 2; q++)
                        mma16816(acc[i][j * 2 + q], af[0][i], bf[0][j][q], bf[0][j][q + 2]);
            #pragma unroll
            for (int i = 0; i < 2; i++)
                #pragma unroll
                for (int j = 0; j < 3; j++)
                    #pragma unroll
                    for (int q = 0; q < 2; q++)
                        mma16816(acc[i][j * 2 + q], af[0][i], bf[1][j][q], bf[1][j][q + 2]);
            #pragma unroll
            for (int i = 0; i < 2; i++)
                #pragma unroll
                for (int j = 0; j < 3; j++)
                    #pragma unroll
                    for (int q = 0; q < 2; q++)
                        mma16816(acc[i][j * 2 + q], af[1][i], bf[0][j][q], bf[0][j][q + 2]);
        }
    }

    // ---- epilogue: acc -> smem, recombine gate triples, GRU update ----
    __syncthreads();
    float* smf = (float*)smraw;
    {
        int g = lane >> 2, tig = lane & 3;
        #pragma unroll
        for (int i = 0; i < 2; i++) {
            int row = m0 + i * 16 + g;
            #pragma unroll
            for (int n = 0; n < 6; n++) {
                int col = n0 + n * 8 + tig * 2;
                *(float2*)&smf[row * LDE + col]       = make_float2(acc[i][n][0], acc[i][n][1]);
                *(float2*)&smf[(row + 8) * LDE + col] = make_float2(acc[i][n][2], acc[i][n][3]);
            }
        }
    }
    __syncthreads();

    int s_idx = dir ? (Sq - 1 - t) : t;
    // 2 consecutive h-columns per thread: 128 rows x 32 pairs / 512 thr = 8 iters
    #pragma unroll 4
    for (int e = 0; e < 8; e++) {
        int idx = e * 512 + tid;
        int row = idx >> 5;            // 0..127
        int sub = (idx & 31) * 2;      // even col in 0..62
        int b = bm + row;
        int tok = (mode == 0) ? src[b * Sq + s_idx] : g_tok[b];
        const float* gi = tab + (size_t)tok * Ntot + bn;
        float2 gh_r = *(float2*)&smf[row * LDE + sub];
        float2 gh_z = *(float2*)&smf[row * LDE + 64 + sub];
        float2 gh_n = *(float2*)&smf[row * LDE + 128 + sub];
        float2 gi_r = *(const float2*)&gi[sub];
        float2 gi_z = *(const float2*)&gi[64 + sub];
        float2 gi_n = *(const float2*)&gi[128 + sub];
        float2 bh_r = *(const float2*)&bh[bn + sub];
        float2 bh_z = *(const float2*)&bh[bn + 64 + sub];
        float2 bh_n = *(const float2*)&bh[bn + 128 + sub];
        int hcol = bx * 64 + sub;
        size_t ho_off = (size_t)b * Hloc + hcol;
        float2 hp = *(const float2*)&hprevf[ho_off];

        float r0 = sigf(gi_r.x + gh_r.x + bh_r.x);
        float r1 = sigf(gi_r.y + gh_r.y + bh_r.y);
        float z0 = sigf(gi_z.x + gh_z.x + bh_z.x);
        float z1 = sigf(gi_z.y + gh_z.y + bh_z.y);
        float n0v = tanhf(gi_n.x + r0 * (gh_n.x + bh_n.x));
        float n1v = tanhf(gi_n.y + r1 * (gh_n.y + bh_n.y));
        float h0 = (1.f - z0) * n0v + z0 * hp.x;
        float h1 = (1.f - z1) * n1v + z1 * hp.y;

        *(float2*)&houtf[ho_off] = make_float2(h0, h1);
        __nv_bfloat16 hh0 = __float2bfloat16(h0);
        __nv_bfloat16 hh1 = __float2bfloat16(h1);
        __nv_bfloat162 vhi; vhi.x = hh0; vhi.y = hh1;
        __nv_bfloat162 vlo;
        vlo.x = __float2bfloat16(h0 - __bfloat162float(hh0));
        vlo.y = __float2bfloat16(h1 - __bfloat162float(hh1));
        *(__nv_bfloat162*)&houthi[ho_off] = vhi;
        *(__nv_bfloat162*)&houtlo[ho_off] = vlo;
    }
}

// ---------------------------------------------------------------------------
// Concat encoder final states -> decoder h0 (ping 0)
// ---------------------------------------------------------------------------
__global__ void concat_kernel()
{
    int i = blockIdx.x * 256 + threadIdx.x;  // < 512*2048
    int b = i >> 11, j = i & 2047;
    float v = (j < Hq) ? g_h_e[0][0][b][j] : g_h_e[1][0][b][j - Hq];
    g_hdec_f[0][b][j] = v;
    __nv_bfloat16 h = __float2bfloat16(v);
    g_hhi_d[0][b][j] = h;
    g_hlo_d[0][b][j] = __float2bfloat16(v - __bfloat162float(h));
}

// ---------------------------------------------------------------------------
// Logits partials via bf16x3 mma: h[512,2048] @ W_fc[128,2048]^T, K-split x16
// grid (16 ksplit, 4 mtile), tile 128x128, K=128/split (2 chunks of 64)
// ---------------------------------------------------------------------------
#define LOG_SMEM (2 * 65536 + 1024)

__global__ __launch_bounds__(256, 1) void logits_mma_kernel(int t)
{
    extern __shared__ char smraw[];
    u32 raw = smem_u32(smraw);
    u32 base = (raw + 1023) & ~1023u;

    int tid = threadIdx.x, wid = tid >> 5, lane = tid & 31;
    int ks = blockIdx.x;
    int bm = blockIdx.y * 128;
    const int K = H2q;
    int kb0 = ks * 128;
    int pb = (t + 1) & 1;

    const __nv_bfloat16* pAh = &g_hhi_d[pb][0][0] + (size_t)bm * K;
    const __nv_bfloat16* pAl = &g_hlo_d[pb][0][0] + (size_t)bm * K;
    const __nv_bfloat16* pBh = &g_Wfc_hi[0][0];
    const __nv_bfloat16* pBl = &g_Wfc_lo[0][0];

    int m0 = (wid >> 2) * 64;
    int n0 = (wid & 3) * 32;

    float acc[4][4][4];
    #pragma unroll
    for (int i = 0; i < 4; i++)
        #pragma unroll
        for (int n = 0; n < 4; n++)
            #pragma unroll
            for (int q = 0; q < 4; q++) acc[i][n][q] = 0.f;

    #define LSTAGE(stg, kb) do {                                             \
        u32 sb_ = base + (stg) * 65536;                                      \
        _Pragma("unroll")                                                    \
        for (int p = 0; p < 16; p++) {                                       \
            int u_ = tid + 256 * p; int row_ = u_ >> 3, c_ = u_ & 7;         \
            int sec_ = row_ >> 7; int r_ = row_ & 127;                       \
            const __nv_bfloat16* g_ =                                        \
                (sec_ == 0 ? pAh : sec_ == 1 ? pAl : sec_ == 2 ? pBh : pBl)  \
                + (size_t)r_ * K + kb0 + (kb) + c_ * 8;                      \
            cp16(sb_ + sec_ * 16384u + swz(r_ * 128 + c_ * 16), g_);         \
        }                                                                    \
    } while (0)

    LSTAGE(0, 0);
    cp_commit();

    #pragma unroll
    for (int c = 0; c < 2; c++) {
        int s = c & 1;
        __syncthreads();
        if (c == 0) { LSTAGE(1, 64); cp_commit(); cp_wait1(); }
        else        { cp_wait0(); }
        __syncthreads();

        u32 buf = base + s * 65536;
        int arow = lane & 15;
        int acol = (lane >> 4) * 16;

        #pragma unroll
        for (int kss = 0; kss < 4; kss++) {
            int obyte = kss * 32 + acol;
            u32 af[2][4][4];
            u32 bf[2][2][4];
            #pragma unroll
            for (int i = 0; i < 4; i++) {
                u32 off = swz((m0 + i * 16 + arow) * 128 + obyte);
                ldsm4(buf + off,         af[0][i][0], af[0][i][1], af[0][i][2], af[0][i][3]);
                ldsm4(buf + 16384 + off, af[1][i][0], af[1][i][1], af[1][i][2], af[1][i][3]);
            }
            #pragma unroll
            for (int j = 0; j < 2; j++) {
                u32 off = swz((n0 + j * 16 + arow) * 128 + obyte);
                ldsm4(buf + 32768 + off, bf[0][j][0], bf[0][j][1], bf[0][j][2], bf[0][j][3]);
                ldsm4(buf + 49152 + off, bf[1][j][0], bf[1][j][1], bf[1][j][2], bf[1][j][3]);
            }
            #pragma unroll
            for (int i = 0; i < 4; i++)
                #pragma unroll
                for (int j = 0; j < 2; j++)
                    #pragma unroll
                    for (int q = 0; q < 2; q++)
                        mma16816(acc[i][j * 2 + q], af[0][i], bf[0][j][q], bf[0][j][q + 2]);
            #pragma unroll
            for (int i = 0; i < 4; i++)
                #pragma unroll
                for (int j = 0; j < 2; j++)
                    #pragma unroll
                    for (int q = 0; q < 2; q++)
                        mma16816(acc[i][j * 2 + q], af[0][i], bf[1][j][q], bf[1][j][q + 2]);
            #pragma unroll
            for (int i = 0; i < 4; i++)
                #pragma unroll
                for (int j = 0; j < 2; j++)
                    #pragma unroll
                    for (int q = 0; q < 2; q++)
                        mma16816(acc[i][j * 2 + q], af[1][i], bf[0][j][q], bf[0][j][q + 2]);
        }
    }

    int g = lane >> 2, tig = lane & 3;
    #pragma unroll
    for (int i = 0; i < 4; i++) {
        int row0 = bm + m0 + i * 16 + g;
        #pragma unroll
        for (int n = 0; n < 4; n++) {
            int col = n0 + n * 8 + tig * 2;
            *(float2*)&g_lpart[ks][row0][col]     = make_float2(acc[i][n][0], acc[i][n][1]);
            *(float2*)&g_lpart[ks][row0 + 8][col] = make_float2(acc[i][n][2], acc[i][n][3]);
        }
    }
}

// ---------------------------------------------------------------------------
// Reduce partials + bias, write logits, argmax -> g_tok
// ---------------------------------------------------------------------------
__global__ __launch_bounds__(128) void reduce_argmax_kernel(
    const float* __restrict__ bfc, float* __restrict__ out, int t)
{
    int b = blockIdx.x;
    int v = threadIdx.x;
    float s = bfc[v];
    #pragma unroll
    for (int ks = 0; ks < 16; ks++) s += g_lpart[ks][b][v];
    out[((size_t)b * (Tq - 1) + t) * Vq + v] = s;

    __shared__ float sv[128];
    __shared__ int   si[128];
    sv[v] = s; si[v] = v;
    __syncthreads();
    #pragma unroll
    for (int off = 64; off > 0; off >>= 1) {
        if (v < off) {
            float o = sv[v + off]; int oi = si[v + off];
            if (o > sv[v] || (o == sv[v] && oi < si[v])) { sv[v] = o; si[v] = oi; }
        }
        __syncthreads();
    }
    if (v == 0) g_tok[b] = si[0];
}

// ---------------------------------------------------------------------------
extern "C" void kernel_launch(void* const* d_in, const int* in_sizes, int n_in,
                              void* d_out, int out_size)
{
    const int*   src     = (const int*)d_in[0];
    const int*   tgt     = (const int*)d_in[1];
    const float* enc_emb = (const float*)d_in[2];
    const float* dec_emb = (const float*)d_in[3];
    const float* W_ih_f  = (const float*)d_in[4];
    const float* W_hh_f  = (const float*)d_in[5];
    const float* b_ih_f  = (const float*)d_in[6];
    const float* b_hh_f  = (const float*)d_in[7];
    const float* W_ih_b  = (const float*)d_in[8];
    const float* W_hh_b  = (const float*)d_in[9];
    const float* b_ih_b  = (const float*)d_in[10];
    const float* b_hh_b  = (const float*)d_in[11];
    const float* W_ih_d  = (const float*)d_in[12];
    const float* W_hh_d  = (const float*)d_in[13];
    const float* b_ih_d  = (const float*)d_in[14];
    const float* b_hh_d  = (const float*)d_in[15];
    const float* W_fc    = (const float*)d_in[16];
    const float* b_fc    = (const float*)d_in[17];
    float* out = (float*)d_out;

    cudaFuncSetAttribute(gru_step_kernel,
                         cudaFuncAttributeMaxDynamicSharedMemorySize, GEMM_SMEM);
    cudaFuncSetAttribute(logits_mma_kernel,
                         cudaFuncAttributeMaxDynamicSharedMemorySize, LOG_SMEM);

    // ONE prep launch: all weight splits (permuted) + bias permutes
    {
        int gx = (G6H * H2q + 255) / 256;     // 49152, covers largest task
        prep_kernel<<<dim3(gx, 5), 256>>>(W_hh_f, W_hh_b, W_hh_d, W_fc,
                                          b_hh_f, b_hh_b, b_hh_d);
    }

    // Projection tables (permuted), init states/tokens
    table_kernel<<<dim3(96, 2, 3), 256>>>(enc_emb, dec_emb,
                                          W_ih_f, b_ih_f, W_ih_b, b_ih_b, W_ih_d, b_ih_d);
    init_kernel<<<4096, 256>>>(tgt);

    // Bidirectional encoder: fused GEMM+GRU, single wave (128 CTAs)
    for (int t = 0; t < Sq; t++)
        gru_step_kernel<<<dim3(16, 4, 2), 512, GEMM_SMEM>>>(0, t, src);

    // decoder h0 = concat(h_fwd, h_bwd)
    concat_kernel<<<4096, 256>>>();

    // Greedy decoder: fused GEMM+GRU (128 CTAs) + mma logits + argmax
    for (int t = 0; t < Tq - 1; t++) {
        gru_step_kernel<<<dim3(32, 4, 1), 512, GEMM_SMEM>>>(1, t, src);
        logits_mma_kernel<<<dim3(16, 4), 256, LOG_SMEM>>>(t);
        reduce_argmax_kernel<<<Bq, 128>>>(b_fc, out, t);
    }
}